// round 10
// baseline (speedup 1.0000x reference)
#include <cuda_runtime.h>
#include <cuda_fp16.h>
#include <math.h>
#include <stdint.h>

#define NROWS 16384
#define DDIM  2048
#define HDIM  512
#define CDIM  65
#define KPAIRS (DDIM / 2)
#define BPADR 96     // padded B rows for ldmatrix groups of 32

// ---------------- scratch (device globals; no allocation) ----------------
__device__ __half        g_h16[NROWS * HDIM];      // post-dropout hidden (fp16)
__device__ __half        g_feat16[NROWS * DDIM];   // feat converted to fp16
__device__ float         g_logits[NROWS * CDIM];
__device__ float         g_lse[NROWS];
__device__ int           g_pred[NROWS];
__device__ float         g_sump[CDIM];
__device__ float         g_ent;
__device__ float         g_ce;
__device__ float         g_csum[CDIM * DDIM];
__device__ int           g_cnt[CDIM];
__device__ int           g_fill[CDIM];             // scatter cursors
__device__ int           g_perm[NROWS];            // rows sorted by class
__device__ unsigned      g_w1Th[HDIM * KPAIRS];    // half2 pairs, [n][k]
__device__ __half        g_w2T16[BPADR * HDIM];    // [n][k] fp16, rows>=CDIM zero
__device__ __half        g_cent16[BPADR * DDIM];   // [c][d] fp16 centroids

// ---------------- helpers ----------------
__device__ __forceinline__ unsigned pack_h2(float a, float b)
{
    __half2 h = __floats2half2_rn(a, b);
    return *reinterpret_cast<unsigned*>(&h);
}

__device__ __forceinline__ unsigned smem_u32(const void* p)
{
    unsigned a;
    asm("{ .reg .u64 t; cvta.to.shared.u64 t, %1; cvt.u32.u64 %0, t; }" : "=r"(a) : "l"(p));
    return a;
}

__device__ __forceinline__ void mma_f16(float c[4],
                                        unsigned a0, unsigned a1, unsigned a2, unsigned a3,
                                        unsigned b0, unsigned b1)
{
    asm volatile(
        "mma.sync.aligned.m16n8k16.row.col.f32.f16.f16.f32 "
        "{%0,%1,%2,%3}, {%4,%5,%6,%7}, {%8,%9}, {%0,%1,%2,%3};"
        : "+f"(c[0]), "+f"(c[1]), "+f"(c[2]), "+f"(c[3])
        : "r"(a0), "r"(a1), "r"(a2), "r"(a3), "r"(b0), "r"(b1));
}

__device__ __forceinline__ void ldsm_x4(unsigned& r0, unsigned& r1, unsigned& r2, unsigned& r3,
                                        unsigned saddr)
{
    asm volatile("ldmatrix.sync.aligned.m8n8.x4.shared.b16 {%0,%1,%2,%3}, [%4];"
                 : "=r"(r0), "=r"(r1), "=r"(r2), "=r"(r3) : "r"(saddr));
}

#define CP_ASYNC16(dst, src) \
    asm volatile("cp.async.cg.shared.global [%0], [%1], 16;" :: "r"(dst), "l"(src))
#define CP_COMMIT() asm volatile("cp.async.commit_group;")
#define CP_WAIT(n)  asm volatile("cp.async.wait_group %0;" :: "n"(n))

// ---------------- threefry2x32 (JAX partitionable, key = (0, 42)) ----------------
__device__ __forceinline__ void threefry2x32_42(unsigned c0, unsigned c1,
                                                unsigned& o0, unsigned& o1)
{
    const unsigned ks0 = 0u;
    const unsigned ks1 = 42u;
    const unsigned ks2 = 0x1BD11BDAu ^ 0u ^ 42u;
    unsigned x0 = c0 + ks0;
    unsigned x1 = c1 + ks1;
#define TF_ROUND(r) { x0 += x1; x1 = (x1 << (r)) | (x1 >> (32 - (r))); x1 ^= x0; }
    TF_ROUND(13) TF_ROUND(15) TF_ROUND(26) TF_ROUND(6)
    x0 += ks1; x1 += ks2 + 1u;
    TF_ROUND(17) TF_ROUND(29) TF_ROUND(16) TF_ROUND(24)
    x0 += ks2; x1 += ks0 + 2u;
    TF_ROUND(13) TF_ROUND(15) TF_ROUND(26) TF_ROUND(6)
    x0 += ks0; x1 += ks1 + 3u;
    TF_ROUND(17) TF_ROUND(29) TF_ROUND(16) TF_ROUND(24)
    x0 += ks1; x1 += ks2 + 4u;
    TF_ROUND(13) TF_ROUND(15) TF_ROUND(26) TF_ROUND(6)
    x0 += ks2; x1 += ks0 + 5u;
#undef TF_ROUND
    o0 = x0; o1 = x1;
}

__device__ __forceinline__ bool keep_bit(unsigned idx)
{
    unsigned a, b;
    threefry2x32_42(0u, idx, a, b);
    return (b >> 31) == 0u;
}

// ============================================================================
// prep: feat->fp16, w1 transpose->fp16, w2 transpose->fp16, zero accumulators
// ============================================================================
#define FEAT_BLOCKS (NROWS * DDIM / (256 * 8))          // 16384
#define W1T_BLOCKS  ((DDIM / 32) * (HDIM / 32))         // 1024
#define W2T_BLOCKS  ((BPADR * HDIM + 255) / 256)        // 192
#define ZERO_BLOCKS ((CDIM * DDIM + 255) / 256)         // 520
#define PREP_BLOCKS (FEAT_BLOCKS + W1T_BLOCKS + W2T_BLOCKS + ZERO_BLOCKS)

__global__ void __launch_bounds__(256) prep_kernel(const float* __restrict__ feat,
                                                   const float* __restrict__ w1,
                                                   const float* __restrict__ w2)
{
    __shared__ float t[32][33];
    const int b = blockIdx.x;
    const int tid = threadIdx.x;

    if (b < FEAT_BLOCKS) {
        size_t i = ((size_t)b * 256 + tid) * 8;
        float4 v0 = *reinterpret_cast<const float4*>(feat + i);
        float4 v1 = *reinterpret_cast<const float4*>(feat + i + 4);
        uint4 o;
        o.x = pack_h2(v0.x, v0.y);
        o.y = pack_h2(v0.z, v0.w);
        o.z = pack_h2(v1.x, v1.y);
        o.w = pack_h2(v1.z, v1.w);
        *reinterpret_cast<uint4*>(&g_feat16[i]) = o;
    } else if (b < FEAT_BLOCKS + W1T_BLOCKS) {
        int q = b - FEAT_BLOCKS;
        int k0 = (q & 63) * 32, n0 = (q >> 6) * 32;
        int x = tid & 31, y = tid >> 5;
#pragma unroll
        for (int i = y; i < 32; i += 8) t[i][x] = w1[(size_t)(k0 + i) * HDIM + n0 + x];
        __syncthreads();
#pragma unroll
        for (int i = y; i < 16; i += 8)
            g_w1Th[(size_t)(n0 + x) * KPAIRS + k0 / 2 + i] = pack_h2(t[2 * i][x], t[2 * i + 1][x]);
    } else if (b < FEAT_BLOCKS + W1T_BLOCKS + W2T_BLOCKS) {
        int i = (b - FEAT_BLOCKS - W1T_BLOCKS) * 256 + tid;
        if (i < BPADR * HDIM) {
            int n = i / HDIM, k = i - n * HDIM;
            g_w2T16[i] = (n < CDIM) ? __float2half_rn(w2[k * CDIM + n]) : __float2half_rn(0.f);
        }
    } else {
        int i = (b - FEAT_BLOCKS - W1T_BLOCKS - W2T_BLOCKS) * 256 + tid;
        if (i < CDIM * DDIM) g_csum[i] = 0.f;
        if (i < CDIM) { g_sump[i] = 0.f; g_cnt[i] = 0; }
        if (i == 0) { g_ent = 0.f; g_ce = 0.f; }
    }
}

// ============================================================================
// GEMM1 (fp16, 2-stage cp.async + ldmatrix): g_h16 = dropout(relu(feat@w1+b1))
// ============================================================================
#define G1_SMEM (2 * 32768)

__global__ void __launch_bounds__(256) gemm1_fp16(const float* __restrict__ bias)
{
    extern __shared__ __align__(1024) char dsm[];
    __shared__ float sb[128];

    const unsigned sbase = smem_u32(dsm);
    const int tid  = threadIdx.x;
    const int lane = tid & 31;
    const int w    = tid >> 5;
    const int g    = lane >> 2;
    const int t    = lane & 3;
    const int wm   = w & 1;
    const int wn   = w >> 1;
    const int brow = blockIdx.y * 128;
    const int bcol = blockIdx.x * 128;

    if (tid < 128) sb[tid] = bias[bcol + tid];

    const int NT = DDIM / 64;           // 32
    const int cr = tid >> 3;
    const int cc = tid & 7;

    auto issue_copy = [&](int kt) {
        const unsigned aoff = (kt & 1) * 32768u;
        const unsigned boff = aoff + 16384u;
        const __half* Ag = &g_feat16[(size_t)brow * DDIM + kt * 64];
        const unsigned* Bg = &g_w1Th[(size_t)bcol * KPAIRS + kt * 32];
#pragma unroll
        for (int i = 0; i < 4; i++) {
            int r = cr + 32 * i;
            unsigned dsw = (unsigned)((cc ^ (r & 7)) << 4);
            CP_ASYNC16(sbase + aoff + r * 128 + dsw, Ag + (size_t)r * DDIM + cc * 8);
            CP_ASYNC16(sbase + boff + r * 128 + dsw, Bg + (size_t)r * KPAIRS + cc * 4);
        }
        CP_COMMIT();
    };

    float acc[4][4][4];
#pragma unroll
    for (int i = 0; i < 4; i++)
#pragma unroll
        for (int j = 0; j < 4; j++)
#pragma unroll
            for (int c = 0; c < 4; c++) acc[i][j][c] = 0.f;

    issue_copy(0);

    for (int kt = 0; kt < NT; kt++) {
        if (kt + 1 < NT) { issue_copy(kt + 1); CP_WAIT(1); }
        else             { CP_WAIT(0); }
        __syncthreads();

        const unsigned aoff = (kt & 1) * 32768u;
        const unsigned boff = aoff + 16384u;

        const int bn = wn * 32 + lane;
        const unsigned bline = sbase + boff + bn * 128;
        const int arl = (lane & 15);
        const int ach = (lane >> 4);

#pragma unroll
        for (int ks = 0; ks < 4; ks++) {
            unsigned b0[4], b1[4];
            {
                int c0 = (2 * ks) ^ (bn & 7);
                int c1 = (2 * ks + 1) ^ (bn & 7);
                ldsm_x4(b0[0], b0[1], b0[2], b0[3], bline + (c0 << 4));
                ldsm_x4(b1[0], b1[1], b1[2], b1[3], bline + (c1 << 4));
            }
#pragma unroll
            for (int mt = 0; mt < 4; mt++) {
                int row = wm * 64 + mt * 16 + arl;
                int ch  = (2 * ks + ach) ^ (row & 7);
                unsigned a0, a1, a2, a3;
                ldsm_x4(a0, a1, a2, a3, sbase + aoff + row * 128 + (ch << 4));
#pragma unroll
                for (int nt = 0; nt < 4; nt++)
                    mma_f16(acc[mt][nt], a0, a1, a2, a3, b0[nt], b1[nt]);
            }
        }
        __syncthreads();
    }

#pragma unroll
    for (int mt = 0; mt < 4; mt++) {
#pragma unroll
        for (int h = 0; h < 2; h++) {
            int row = brow + wm * 64 + mt * 16 + g + 8 * h;
#pragma unroll
            for (int nt = 0; nt < 4; nt++) {
                int colL = wn * 32 + nt * 8 + 2 * t;
                unsigned i0 = (unsigned)(row * HDIM + bcol + colL);
                float v0 = fmaxf(acc[mt][nt][2 * h + 0] + sb[colL], 0.f);
                float v1 = fmaxf(acc[mt][nt][2 * h + 1] + sb[colL + 1], 0.f);
                unsigned o = pack_h2(keep_bit(i0)     ? (v0 + v0) : 0.f,
                                     keep_bit(i0 + 1) ? (v1 + v1) : 0.f);
                *reinterpret_cast<unsigned*>(&g_h16[i0]) = o;
            }
        }
    }
}

// ============================================================================
// logits (fp16, 2-stage): A = g_h16, B = g_w2T16; fused stats/argmax/counts.
// ============================================================================
#define SK_SMEM 57344

__global__ void __launch_bounds__(256) logits_f16(const float* __restrict__ b2)
{
    extern __shared__ __align__(1024) char dsm[];
    const unsigned sbase = smem_u32(dsm);
    const int tid  = threadIdx.x;
    const int lane = tid & 31;
    const int w    = tid >> 5;
    const int g    = lane >> 2;
    const int t    = lane & 3;
    const int row0 = blockIdx.x * 128;
    const int cr   = tid >> 3;
    const int cc   = tid & 7;

    auto issue_copy = [&](int kt) {
        const unsigned aoff = (kt & 1) * 28672u;
        const unsigned boff = aoff + 16384u;
        const __half* Ag = &g_h16[(size_t)row0 * HDIM + kt * 64];
        const __half* Bg = &g_w2T16[kt * 64];
#pragma unroll
        for (int i = 0; i < 4; i++) {
            int r = cr + 32 * i;
            unsigned dsw = (unsigned)((cc ^ (r & 7)) << 4);
            CP_ASYNC16(sbase + aoff + r * 128 + dsw, Ag + (size_t)r * HDIM + cc * 8);
        }
#pragma unroll
        for (int i = 0; i < 3; i++) {
            int q = tid + 256 * i;
            int r = q >> 3, c = q & 7;
            unsigned dsw = (unsigned)((c ^ (r & 7)) << 4);
            CP_ASYNC16(sbase + boff + r * 128 + dsw, Bg + (size_t)r * HDIM + c * 8);
        }
        CP_COMMIT();
    };

    float acc[10][4];
#pragma unroll
    for (int n = 0; n < 10; n++)
#pragma unroll
        for (int c = 0; c < 4; c++) acc[n][c] = 0.f;

    issue_copy(0);
    const int NT = HDIM / 64;   // 8
    for (int kt = 0; kt < NT; kt++) {
        if (kt + 1 < NT) { issue_copy(kt + 1); CP_WAIT(1); }
        else             { CP_WAIT(0); }
        __syncthreads();

        const unsigned aoff = (kt & 1) * 28672u;
        const unsigned boff = aoff + 16384u;
        const int arl = lane & 15;
        const int ach = lane >> 4;

#pragma unroll
        for (int ks = 0; ks < 4; ks++) {
            unsigned b0[12], b1[12];
#pragma unroll
            for (int gr = 0; gr < 3; gr++) {
                int bn = gr * 32 + lane;
                unsigned bline = sbase + boff + bn * 128;
                int c0 = (2 * ks) ^ (bn & 7);
                int c1 = (2 * ks + 1) ^ (bn & 7);
                ldsm_x4(b0[gr*4+0], b0[gr*4+1], b0[gr*4+2], b0[gr*4+3], bline + (c0 << 4));
                ldsm_x4(b1[gr*4+0], b1[gr*4+1], b1[gr*4+2], b1[gr*4+3], bline + (c1 << 4));
            }
            int row = w * 16 + arl;
            int ch  = (2 * ks + ach) ^ (row & 7);
            unsigned a0, a1, a2, a3;
            ldsm_x4(a0, a1, a2, a3, sbase + aoff + row * 128 + (ch << 4));
#pragma unroll
            for (int nt = 0; nt < 10; nt++)
                mma_f16(acc[nt], a0, a1, a2, a3, b0[nt], b1[nt]);
        }
        __syncthreads();
    }

    float su[10][2];
#pragma unroll
    for (int n = 0; n < 10; n++) { su[n][0] = 0.f; su[n][1] = 0.f; }
    float entL = 0.f;

#pragma unroll
    for (int half = 0; half < 2; half++) {
        int row = row0 + w * 16 + g + 8 * half;
        int ci  = 2 * half;

        float v[10][2];
        float m = -1e30f;
#pragma unroll
        for (int nt = 0; nt < 10; nt++)
#pragma unroll
            for (int j = 0; j < 2; j++) {
                int col = nt * 8 + 2 * t + j;
                v[nt][j] = (col < CDIM) ? acc[nt][ci + j] + b2[col] : -1e30f;
                m = fmaxf(m, v[nt][j]);
            }
        m = fmaxf(m, __shfl_xor_sync(0xffffffffu, m, 1));
        m = fmaxf(m, __shfl_xor_sync(0xffffffffu, m, 2));

        float s = 0.f;
#pragma unroll
        for (int nt = 0; nt < 10; nt++)
#pragma unroll
            for (int j = 0; j < 2; j++) {
                int col = nt * 8 + 2 * t + j;
                if (col < CDIM) s += expf(v[nt][j] - m);
            }
        s += __shfl_xor_sync(0xffffffffu, s, 1);
        s += __shfl_xor_sync(0xffffffffu, s, 2);
        float lse = m + logf(s);

        float bv = -1e30f; int bi = CDIM;
#pragma unroll
        for (int nt = 0; nt < 10; nt++)
#pragma unroll
            for (int j = 0; j < 2; j++) {
                int col = nt * 8 + 2 * t + j;
                if (col < CDIM) {
                    float p = expf(v[nt][j] - lse);
                    entL += p * logf(p + 1e-6f);
                    su[nt][j] += p;
                    g_logits[row * CDIM + col] = v[nt][j];
                    if (v[nt][j] > bv || (v[nt][j] == bv && col < bi)) { bv = v[nt][j]; bi = col; }
                }
            }
#pragma unroll
        for (int o = 1; o <= 2; o <<= 1) {
            float ov = __shfl_xor_sync(0xffffffffu, bv, o);
            int   oi = __shfl_xor_sync(0xffffffffu, bi, o);
            if (ov > bv || (ov == bv && oi < bi)) { bv = ov; bi = oi; }
        }
        if (t == 0) {
            g_lse[row]  = lse;
            g_pred[row] = bi;
            atomicAdd(&g_cnt[bi], 1);
        }
    }

#pragma unroll
    for (int o = 16; o > 0; o >>= 1) entL += __shfl_xor_sync(0xffffffffu, entL, o);
    if (lane == 0) atomicAdd(&g_ent, entL);

#pragma unroll
    for (int o = 4; o <= 16; o <<= 1)
#pragma unroll
        for (int nt = 0; nt < 10; nt++)
#pragma unroll
            for (int j = 0; j < 2; j++)
                su[nt][j] += __shfl_xor_sync(0xffffffffu, su[nt][j], o);
    if (g == 0) {
#pragma unroll
        for (int nt = 0; nt < 10; nt++)
#pragma unroll
            for (int j = 0; j < 2; j++) {
                int col = nt * 8 + 2 * t + j;
                if (col < CDIM) atomicAdd(&g_sump[col], su[nt][j]);
            }
    }
}

// ---- scan: exclusive prefix of g_cnt -> g_fill (single block) ----
__global__ void scan_kernel()
{
    if (threadIdx.x == 0) {
        int acc = 0;
        for (int c = 0; c < CDIM; c++) {
            g_fill[c] = acc;
            acc += g_cnt[c];
        }
    }
}

// ---- scatter: counting-sort rows by class into g_perm ----
__global__ void __launch_bounds__(256) scatter_kernel()
{
    int i = blockIdx.x * 256 + threadIdx.x;
    if (i < NROWS) {
        int c = g_pred[i];
        int pos = atomicAdd(&g_fill[c], 1);
        g_perm[pos] = i;
    }
}

// ---- segsum over class-sorted rows: register run accumulation, no smem acc ----
#define SEG_ROWS 512
__global__ void __launch_bounds__(128) segsum_sorted()
{
    __shared__ int sperm[SEG_ROWS];
    __shared__ int scls[SEG_ROWS];

    const int t    = threadIdx.x;
    const int col2 = blockIdx.x * 128 + t;          // half2 column
    const int r0   = blockIdx.y * SEG_ROWS;

    for (int i = t; i < SEG_ROWS; i += 128) {
        int p = g_perm[r0 + i];
        sperm[i] = p;
        scls[i]  = g_pred[p];
    }
    __syncthreads();

    const unsigned* f2 = reinterpret_cast<const unsigned*>(g_feat16);
    float rx = 0.f, ry = 0.f;
    int cur = scls[0];
    unsigned u = f2[(size_t)sperm[0] * (DDIM / 2) + col2];

    for (int i = 0; i < SEG_ROWS; i++) {
        unsigned un = 0;
        if (i + 1 < SEG_ROWS) un = f2[(size_t)sperm[i + 1] * (DDIM / 2) + col2];
        int c = scls[i];
        if (c != cur) {
            atomicAdd(&g_csum[cur * DDIM + 2 * col2],     rx);
            atomicAdd(&g_csum[cur * DDIM + 2 * col2 + 1], ry);
            rx = 0.f; ry = 0.f; cur = c;
        }
        float2 v = __half22float2(*reinterpret_cast<__half2*>(&u));
        rx += v.x; ry += v.y;
        u = un;
    }
    atomicAdd(&g_csum[cur * DDIM + 2 * col2],     rx);
    atomicAdd(&g_csum[cur * DDIM + 2 * col2 + 1], ry);
}

// ---- finalize centroids (normalized), K-major fp16; grid = 96 ----
__global__ void __launch_bounds__(256) centroid_f16()
{
    __shared__ float red[256];
    const int c = blockIdx.x;
    const int t = threadIdx.x;
    if (c >= CDIM) {
        for (int d = t; d < DDIM; d += 256) g_cent16[(size_t)c * DDIM + d] = __float2half_rn(0.f);
        return;
    }
    const int cnt = g_cnt[c];
    const float denom = fmaxf((float)cnt, 1.f);

    float ssq = 0.f;
    for (int d = t; d < DDIM; d += 256) {
        float mv = g_csum[c * DDIM + d] / denom;
        ssq += mv * mv;
    }
    red[t] = ssq;
    __syncthreads();
    for (int o = 128; o > 0; o >>= 1) { if (t < o) red[t] += red[t + o]; __syncthreads(); }
    float nrm   = sqrtf(red[0]);
    float scale = (cnt > 0) ? 1.f / (denom * fmaxf(nrm, 1e-12f)) : 0.f;

    for (int d = t; d < DDIM; d += 256)
        g_cent16[(size_t)c * DDIM + d] = __float2half_rn(g_csum[c * DDIM + d] * scale);
}

// ---- sim (fp16, 2-stage): A = g_feat16, B = g_cent16 ; fused argmax + CE ----
__global__ void __launch_bounds__(256) sim_f16()
{
    extern __shared__ __align__(1024) char dsm[];
    const unsigned sbase = smem_u32(dsm);
    const int tid  = threadIdx.x;
    const int lane = tid & 31;
    const int w    = tid >> 5;
    const int t    = lane & 3;
    const int row0 = blockIdx.x * 128;
    const int cr   = tid >> 3;
    const int cc   = tid & 7;

    auto issue_copy = [&](int kt) {
        const unsigned aoff = (kt & 1) * 28672u;
        const unsigned boff = aoff + 16384u;
        const __half* Ag = &g_feat16[(size_t)row0 * DDIM + kt * 64];
        const __half* Bg = &g_cent16[kt * 64];
#pragma unroll
        for (int i = 0; i < 4; i++) {
            int r = cr + 32 * i;
            unsigned dsw = (unsigned)((cc ^ (r & 7)) << 4);
            CP_ASYNC16(sbase + aoff + r * 128 + dsw, Ag + (size_t)r * DDIM + cc * 8);
        }
#pragma unroll
        for (int i = 0; i < 3; i++) {
            int q = tid + 256 * i;
            int r = q >> 3, c = q & 7;
            unsigned dsw = (unsigned)((c ^ (r & 7)) << 4);
            CP_ASYNC16(sbase + boff + r * 128 + dsw, Bg + (size_t)r * DDIM + c * 8);
        }
        CP_COMMIT();
    };

    float acc[10][4];
#pragma unroll
    for (int n = 0; n < 10; n++)
#pragma unroll
        for (int c = 0; c < 4; c++) acc[n][c] = 0.f;

    issue_copy(0);
    const int NT = DDIM / 64;   // 32
    for (int kt = 0; kt < NT; kt++) {
        if (kt + 1 < NT) { issue_copy(kt + 1); CP_WAIT(1); }
        else             { CP_WAIT(0); }
        __syncthreads();

        const unsigned aoff = (kt & 1) * 28672u;
        const unsigned boff = aoff + 16384u;
        const int arl = lane & 15;
        const int ach = lane >> 4;

#pragma unroll
        for (int ks = 0; ks < 4; ks++) {
            unsigned b0[12], b1[12];
#pragma unroll
            for (int gr = 0; gr < 3; gr++) {
                int bn = gr * 32 + lane;
                unsigned bline = sbase + boff + bn * 128;
                int c0 = (2 * ks) ^ (bn & 7);
                int c1 = (2 * ks + 1) ^ (bn & 7);
                ldsm_x4(b0[gr*4+0], b0[gr*4+1], b0[gr*4+2], b0[gr*4+3], bline + (c0 << 4));
                ldsm_x4(b1[gr*4+0], b1[gr*4+1], b1[gr*4+2], b1[gr*4+3], bline + (c1 << 4));
            }
            int row = w * 16 + arl;
            int ch  = (2 * ks + ach) ^ (row & 7);
            unsigned a0, a1, a2, a3;
            ldsm_x4(a0, a1, a2, a3, sbase + aoff + row * 128 + (ch << 4));
#pragma unroll
            for (int nt = 0; nt < 10; nt++)
                mma_f16(acc[nt], a0, a1, a2, a3, b0[nt], b1[nt]);
        }
        __syncthreads();
    }

    const int g = lane >> 2;
    float ceL = 0.f;
#pragma unroll
    for (int half = 0; half < 2; half++) {
        int row = row0 + w * 16 + g + 8 * half;
        int ci  = 2 * half;

        float bv = -1e30f; int bi = CDIM;
#pragma unroll
        for (int nt = 0; nt < 10; nt++)
#pragma unroll
            for (int j = 0; j < 2; j++) {
                int col = nt * 8 + 2 * t + j;
                if (col < CDIM) {
                    float vv = acc[nt][ci + j];
                    if (vv > bv || (vv == bv && col < bi)) { bv = vv; bi = col; }
                }
            }
#pragma unroll
        for (int o = 1; o <= 2; o <<= 1) {
            float ov = __shfl_xor_sync(0xffffffffu, bv, o);
            int   oi = __shfl_xor_sync(0xffffffffu, bi, o);
            if (ov > bv || (ov == bv && oi < bi)) { bv = ov; bi = oi; }
        }
        if (t == 0)
            ceL += g_lse[row] - g_logits[row * CDIM + bi];
    }
#pragma unroll
    for (int o = 16; o > 0; o >>= 1) ceL += __shfl_xor_sync(0xffffffffu, ceL, o);
    if (lane == 0) atomicAdd(&g_ce, ceL);
}

// ---------------- final scalar ----------------
__global__ void finalize_kernel(float* __restrict__ out)
{
    __shared__ float red[128];
    int t = threadIdx.x;
    float v = 0.f;
    if (t < CDIM) {
        float mp = g_sump[t] * (1.f / NROWS);
        v = mp * logf(mp + 1e-6f);
    }
    red[t] = v;
    __syncthreads();
    for (int o = 64; o > 0; o >>= 1) { if (t < o) red[t] += red[t + o]; __syncthreads(); }
    if (t == 0) {
        float entropy = -g_ent * (1.f / NROWS);
        float ce      =  g_ce  * (1.f / NROWS);
        out[0] = entropy + red[0] + 0.3f * ce;
    }
}

// ---------------- launch ----------------
extern "C" void kernel_launch(void* const* d_in, const int* in_sizes, int n_in,
                              void* d_out, int out_size)
{
    const float* feat = (const float*)d_in[0];
    const float* w1   = (const float*)d_in[1];
    const float* b1   = (const float*)d_in[2];
    const float* w2   = (const float*)d_in[3];
    const float* b2   = (const float*)d_in[4];
    float* out = (float*)d_out;

    cudaFuncSetAttribute(gemm1_fp16, cudaFuncAttributeMaxDynamicSharedMemorySize, G1_SMEM);
    cudaFuncSetAttribute(logits_f16, cudaFuncAttributeMaxDynamicSharedMemorySize, SK_SMEM);
    cudaFuncSetAttribute(sim_f16,    cudaFuncAttributeMaxDynamicSharedMemorySize, SK_SMEM);

    prep_kernel<<<PREP_BLOCKS, 256>>>(feat, w1, w2);
    gemm1_fp16<<<dim3(HDIM / 128, NROWS / 128), 256, G1_SMEM>>>(b1);
    logits_f16<<<NROWS / 128, 256, SK_SMEM>>>(b2);
    scan_kernel<<<1, 32>>>();
    scatter_kernel<<<NROWS / 256, 256>>>();
    segsum_sorted<<<dim3(DDIM / 256, NROWS / SEG_ROWS), 128>>>();
    centroid_f16<<<BPADR, 256>>>();
    sim_f16<<<NROWS / 128, 256, SK_SMEM>>>();
    finalize_kernel<<<1, 128>>>(out);
}

// round 11
// speedup vs baseline: 1.0532x; 1.0532x over previous
#include <cuda_runtime.h>
#include <cuda_fp16.h>
#include <math.h>
#include <stdint.h>

#define NROWS 16384
#define DDIM  2048
#define HDIM  512
#define CDIM  65
#define KPAIRS (DDIM / 2)
#define BPADR 96     // padded B rows for ldmatrix groups of 32

// ---------------- scratch (device globals; no allocation) ----------------
__device__ __half        g_h16[NROWS * HDIM];      // post-dropout hidden (fp16)
__device__ __half        g_feat16[NROWS * DDIM];   // feat converted to fp16
__device__ float         g_logits[NROWS * CDIM];
__device__ float         g_lse[NROWS];
__device__ int           g_pred[NROWS];
__device__ float         g_sump[CDIM];
__device__ float         g_ent;
__device__ float         g_ce;
__device__ float         g_csum[CDIM * DDIM];
__device__ int           g_cnt[CDIM];
__device__ int           g_fill[CDIM];             // scatter cursors
__device__ int           g_start[CDIM + 1];        // class start offsets
__device__ int           g_perm[NROWS];            // rows sorted by class
__device__ unsigned      g_w1Th[HDIM * KPAIRS];    // half2 pairs, [n][k]
__device__ __half        g_w2T16[BPADR * HDIM];    // [n][k] fp16, rows>=CDIM zero
__device__ __half        g_cent16[BPADR * DDIM];   // [c][d] fp16 centroids

// ---------------- helpers ----------------
__device__ __forceinline__ unsigned pack_h2(float a, float b)
{
    __half2 h = __floats2half2_rn(a, b);
    return *reinterpret_cast<unsigned*>(&h);
}

__device__ __forceinline__ unsigned smem_u32(const void* p)
{
    unsigned a;
    asm("{ .reg .u64 t; cvta.to.shared.u64 t, %1; cvt.u32.u64 %0, t; }" : "=r"(a) : "l"(p));
    return a;
}

__device__ __forceinline__ void mma_f16(float c[4],
                                        unsigned a0, unsigned a1, unsigned a2, unsigned a3,
                                        unsigned b0, unsigned b1)
{
    asm volatile(
        "mma.sync.aligned.m16n8k16.row.col.f32.f16.f16.f32 "
        "{%0,%1,%2,%3}, {%4,%5,%6,%7}, {%8,%9}, {%0,%1,%2,%3};"
        : "+f"(c[0]), "+f"(c[1]), "+f"(c[2]), "+f"(c[3])
        : "r"(a0), "r"(a1), "r"(a2), "r"(a3), "r"(b0), "r"(b1));
}

__device__ __forceinline__ void ldsm_x4(unsigned& r0, unsigned& r1, unsigned& r2, unsigned& r3,
                                        unsigned saddr)
{
    asm volatile("ldmatrix.sync.aligned.m8n8.x4.shared.b16 {%0,%1,%2,%3}, [%4];"
                 : "=r"(r0), "=r"(r1), "=r"(r2), "=r"(r3) : "r"(saddr));
}

#define CP_ASYNC16(dst, src) \
    asm volatile("cp.async.cg.shared.global [%0], [%1], 16;" :: "r"(dst), "l"(src))
#define CP_COMMIT() asm volatile("cp.async.commit_group;")
#define CP_WAIT(n)  asm volatile("cp.async.wait_group %0;" :: "n"(n))

// ---------------- threefry2x32 (JAX partitionable, key = (0, 42)) ----------------
__device__ __forceinline__ void threefry2x32_42(unsigned c0, unsigned c1,
                                                unsigned& o0, unsigned& o1)
{
    const unsigned ks0 = 0u;
    const unsigned ks1 = 42u;
    const unsigned ks2 = 0x1BD11BDAu ^ 0u ^ 42u;
    unsigned x0 = c0 + ks0;
    unsigned x1 = c1 + ks1;
#define TF_ROUND(r) { x0 += x1; x1 = (x1 << (r)) | (x1 >> (32 - (r))); x1 ^= x0; }
    TF_ROUND(13) TF_ROUND(15) TF_ROUND(26) TF_ROUND(6)
    x0 += ks1; x1 += ks2 + 1u;
    TF_ROUND(17) TF_ROUND(29) TF_ROUND(16) TF_ROUND(24)
    x0 += ks2; x1 += ks0 + 2u;
    TF_ROUND(13) TF_ROUND(15) TF_ROUND(26) TF_ROUND(6)
    x0 += ks0; x1 += ks1 + 3u;
    TF_ROUND(17) TF_ROUND(29) TF_ROUND(16) TF_ROUND(24)
    x0 += ks1; x1 += ks2 + 4u;
    TF_ROUND(13) TF_ROUND(15) TF_ROUND(26) TF_ROUND(6)
    x0 += ks2; x1 += ks0 + 5u;
#undef TF_ROUND
    o0 = x0; o1 = x1;
}

__device__ __forceinline__ bool keep_bit(unsigned idx)
{
    unsigned a, b;
    threefry2x32_42(0u, idx, a, b);
    return (b >> 31) == 0u;
}

// ============================================================================
// prep: feat->fp16, w1 transpose->fp16, w2 transpose->fp16, zero accumulators
// ============================================================================
#define FEAT_BLOCKS (NROWS * DDIM / (256 * 8))          // 16384
#define W1T_BLOCKS  ((DDIM / 32) * (HDIM / 32))         // 1024
#define W2T_BLOCKS  ((BPADR * HDIM + 255) / 256)        // 192
#define PREP_BLOCKS (FEAT_BLOCKS + W1T_BLOCKS + W2T_BLOCKS + 1)

__global__ void __launch_bounds__(256) prep_kernel(const float* __restrict__ feat,
                                                   const float* __restrict__ w1,
                                                   const float* __restrict__ w2)
{
    __shared__ float t[32][33];
    const int b = blockIdx.x;
    const int tid = threadIdx.x;

    if (b < FEAT_BLOCKS) {
        size_t i = ((size_t)b * 256 + tid) * 8;
        float4 v0 = *reinterpret_cast<const float4*>(feat + i);
        float4 v1 = *reinterpret_cast<const float4*>(feat + i + 4);
        uint4 o;
        o.x = pack_h2(v0.x, v0.y);
        o.y = pack_h2(v0.z, v0.w);
        o.z = pack_h2(v1.x, v1.y);
        o.w = pack_h2(v1.z, v1.w);
        *reinterpret_cast<uint4*>(&g_feat16[i]) = o;
    } else if (b < FEAT_BLOCKS + W1T_BLOCKS) {
        int q = b - FEAT_BLOCKS;
        int k0 = (q & 63) * 32, n0 = (q >> 6) * 32;
        int x = tid & 31, y = tid >> 5;
#pragma unroll
        for (int i = y; i < 32; i += 8) t[i][x] = w1[(size_t)(k0 + i) * HDIM + n0 + x];
        __syncthreads();
#pragma unroll
        for (int i = y; i < 16; i += 8)
            g_w1Th[(size_t)(n0 + x) * KPAIRS + k0 / 2 + i] = pack_h2(t[2 * i][x], t[2 * i + 1][x]);
    } else if (b < FEAT_BLOCKS + W1T_BLOCKS + W2T_BLOCKS) {
        int i = (b - FEAT_BLOCKS - W1T_BLOCKS) * 256 + tid;
        if (i < BPADR * HDIM) {
            int n = i / HDIM, k = i - n * HDIM;
            g_w2T16[i] = (n < CDIM) ? __float2half_rn(w2[k * CDIM + n]) : __float2half_rn(0.f);
        }
    } else {
        if (tid < CDIM) { g_sump[tid] = 0.f; g_cnt[tid] = 0; }
        if (tid == 0) { g_ent = 0.f; g_ce = 0.f; }
    }
}

// ============================================================================
// GEMM1 (fp16, 2-stage cp.async + ldmatrix): g_h16 = dropout(relu(feat@w1+b1))
// ============================================================================
#define G1_SMEM (2 * 32768)

__global__ void __launch_bounds__(256) gemm1_fp16(const float* __restrict__ bias)
{
    extern __shared__ __align__(1024) char dsm[];
    __shared__ float sb[128];

    const unsigned sbase = smem_u32(dsm);
    const int tid  = threadIdx.x;
    const int lane = tid & 31;
    const int w    = tid >> 5;
    const int g    = lane >> 2;
    const int t    = lane & 3;
    const int wm   = w & 1;
    const int wn   = w >> 1;
    const int brow = blockIdx.y * 128;
    const int bcol = blockIdx.x * 128;

    if (tid < 128) sb[tid] = bias[bcol + tid];

    const int NT = DDIM / 64;           // 32
    const int cr = tid >> 3;
    const int cc = tid & 7;

    auto issue_copy = [&](int kt) {
        const unsigned aoff = (kt & 1) * 32768u;
        const unsigned boff = aoff + 16384u;
        const __half* Ag = &g_feat16[(size_t)brow * DDIM + kt * 64];
        const unsigned* Bg = &g_w1Th[(size_t)bcol * KPAIRS + kt * 32];
#pragma unroll
        for (int i = 0; i < 4; i++) {
            int r = cr + 32 * i;
            unsigned dsw = (unsigned)((cc ^ (r & 7)) << 4);
            CP_ASYNC16(sbase + aoff + r * 128 + dsw, Ag + (size_t)r * DDIM + cc * 8);
            CP_ASYNC16(sbase + boff + r * 128 + dsw, Bg + (size_t)r * KPAIRS + cc * 4);
        }
        CP_COMMIT();
    };

    float acc[4][4][4];
#pragma unroll
    for (int i = 0; i < 4; i++)
#pragma unroll
        for (int j = 0; j < 4; j++)
#pragma unroll
            for (int c = 0; c < 4; c++) acc[i][j][c] = 0.f;

    issue_copy(0);

    for (int kt = 0; kt < NT; kt++) {
        if (kt + 1 < NT) { issue_copy(kt + 1); CP_WAIT(1); }
        else             { CP_WAIT(0); }
        __syncthreads();

        const unsigned aoff = (kt & 1) * 32768u;
        const unsigned boff = aoff + 16384u;

        const int bn = wn * 32 + lane;
        const unsigned bline = sbase + boff + bn * 128;
        const int arl = (lane & 15);
        const int ach = (lane >> 4);

#pragma unroll
        for (int ks = 0; ks < 4; ks++) {
            unsigned b0[4], b1[4];
            {
                int c0 = (2 * ks) ^ (bn & 7);
                int c1 = (2 * ks + 1) ^ (bn & 7);
                ldsm_x4(b0[0], b0[1], b0[2], b0[3], bline + (c0 << 4));
                ldsm_x4(b1[0], b1[1], b1[2], b1[3], bline + (c1 << 4));
            }
#pragma unroll
            for (int mt = 0; mt < 4; mt++) {
                int row = wm * 64 + mt * 16 + arl;
                int ch  = (2 * ks + ach) ^ (row & 7);
                unsigned a0, a1, a2, a3;
                ldsm_x4(a0, a1, a2, a3, sbase + aoff + row * 128 + (ch << 4));
#pragma unroll
                for (int nt = 0; nt < 4; nt++)
                    mma_f16(acc[mt][nt], a0, a1, a2, a3, b0[nt], b1[nt]);
            }
        }
        __syncthreads();
    }

#pragma unroll
    for (int mt = 0; mt < 4; mt++) {
#pragma unroll
        for (int h = 0; h < 2; h++) {
            int row = brow + wm * 64 + mt * 16 + g + 8 * h;
#pragma unroll
            for (int nt = 0; nt < 4; nt++) {
                int colL = wn * 32 + nt * 8 + 2 * t;
                unsigned i0 = (unsigned)(row * HDIM + bcol + colL);
                float v0 = fmaxf(acc[mt][nt][2 * h + 0] + sb[colL], 0.f);
                float v1 = fmaxf(acc[mt][nt][2 * h + 1] + sb[colL + 1], 0.f);
                unsigned o = pack_h2(keep_bit(i0)     ? (v0 + v0) : 0.f,
                                     keep_bit(i0 + 1) ? (v1 + v1) : 0.f);
                *reinterpret_cast<unsigned*>(&g_h16[i0]) = o;
            }
        }
    }
}

// ============================================================================
// logits (fp16, 2-stage): A = g_h16, B = g_w2T16; fused stats/argmax/counts.
// ============================================================================
#define SK_SMEM 57344

__global__ void __launch_bounds__(256) logits_f16(const float* __restrict__ b2)
{
    extern __shared__ __align__(1024) char dsm[];
    const unsigned sbase = smem_u32(dsm);
    const int tid  = threadIdx.x;
    const int lane = tid & 31;
    const int w    = tid >> 5;
    const int g    = lane >> 2;
    const int t    = lane & 3;
    const int row0 = blockIdx.x * 128;
    const int cr   = tid >> 3;
    const int cc   = tid & 7;

    auto issue_copy = [&](int kt) {
        const unsigned aoff = (kt & 1) * 28672u;
        const unsigned boff = aoff + 16384u;
        const __half* Ag = &g_h16[(size_t)row0 * HDIM + kt * 64];
        const __half* Bg = &g_w2T16[kt * 64];
#pragma unroll
        for (int i = 0; i < 4; i++) {
            int r = cr + 32 * i;
            unsigned dsw = (unsigned)((cc ^ (r & 7)) << 4);
            CP_ASYNC16(sbase + aoff + r * 128 + dsw, Ag + (size_t)r * HDIM + cc * 8);
        }
#pragma unroll
        for (int i = 0; i < 3; i++) {
            int q = tid + 256 * i;
            int r = q >> 3, c = q & 7;
            unsigned dsw = (unsigned)((c ^ (r & 7)) << 4);
            CP_ASYNC16(sbase + boff + r * 128 + dsw, Bg + (size_t)r * HDIM + c * 8);
        }
        CP_COMMIT();
    };

    float acc[10][4];
#pragma unroll
    for (int n = 0; n < 10; n++)
#pragma unroll
        for (int c = 0; c < 4; c++) acc[n][c] = 0.f;

    issue_copy(0);
    const int NT = HDIM / 64;   // 8
    for (int kt = 0; kt < NT; kt++) {
        if (kt + 1 < NT) { issue_copy(kt + 1); CP_WAIT(1); }
        else             { CP_WAIT(0); }
        __syncthreads();

        const unsigned aoff = (kt & 1) * 28672u;
        const unsigned boff = aoff + 16384u;
        const int arl = lane & 15;
        const int ach = lane >> 4;

#pragma unroll
        for (int ks = 0; ks < 4; ks++) {
            unsigned b0[12], b1[12];
#pragma unroll
            for (int gr = 0; gr < 3; gr++) {
                int bn = gr * 32 + lane;
                unsigned bline = sbase + boff + bn * 128;
                int c0 = (2 * ks) ^ (bn & 7);
                int c1 = (2 * ks + 1) ^ (bn & 7);
                ldsm_x4(b0[gr*4+0], b0[gr*4+1], b0[gr*4+2], b0[gr*4+3], bline + (c0 << 4));
                ldsm_x4(b1[gr*4+0], b1[gr*4+1], b1[gr*4+2], b1[gr*4+3], bline + (c1 << 4));
            }
            int row = w * 16 + arl;
            int ch  = (2 * ks + ach) ^ (row & 7);
            unsigned a0, a1, a2, a3;
            ldsm_x4(a0, a1, a2, a3, sbase + aoff + row * 128 + (ch << 4));
#pragma unroll
            for (int nt = 0; nt < 10; nt++)
                mma_f16(acc[nt], a0, a1, a2, a3, b0[nt], b1[nt]);
        }
        __syncthreads();
    }

    float su[10][2];
#pragma unroll
    for (int n = 0; n < 10; n++) { su[n][0] = 0.f; su[n][1] = 0.f; }
    float entL = 0.f;

#pragma unroll
    for (int half = 0; half < 2; half++) {
        int row = row0 + w * 16 + g + 8 * half;
        int ci  = 2 * half;

        float v[10][2];
        float m = -1e30f;
#pragma unroll
        for (int nt = 0; nt < 10; nt++)
#pragma unroll
            for (int j = 0; j < 2; j++) {
                int col = nt * 8 + 2 * t + j;
                v[nt][j] = (col < CDIM) ? acc[nt][ci + j] + b2[col] : -1e30f;
                m = fmaxf(m, v[nt][j]);
            }
        m = fmaxf(m, __shfl_xor_sync(0xffffffffu, m, 1));
        m = fmaxf(m, __shfl_xor_sync(0xffffffffu, m, 2));

        float s = 0.f;
#pragma unroll
        for (int nt = 0; nt < 10; nt++)
#pragma unroll
            for (int j = 0; j < 2; j++) {
                int col = nt * 8 + 2 * t + j;
                if (col < CDIM) s += expf(v[nt][j] - m);
            }
        s += __shfl_xor_sync(0xffffffffu, s, 1);
        s += __shfl_xor_sync(0xffffffffu, s, 2);
        float lse = m + logf(s);

        float bv = -1e30f; int bi = CDIM;
#pragma unroll
        for (int nt = 0; nt < 10; nt++)
#pragma unroll
            for (int j = 0; j < 2; j++) {
                int col = nt * 8 + 2 * t + j;
                if (col < CDIM) {
                    float p = expf(v[nt][j] - lse);
                    entL += p * logf(p + 1e-6f);
                    su[nt][j] += p;
                    g_logits[row * CDIM + col] = v[nt][j];
                    if (v[nt][j] > bv || (v[nt][j] == bv && col < bi)) { bv = v[nt][j]; bi = col; }
                }
            }
#pragma unroll
        for (int o = 1; o <= 2; o <<= 1) {
            float ov = __shfl_xor_sync(0xffffffffu, bv, o);
            int   oi = __shfl_xor_sync(0xffffffffu, bi, o);
            if (ov > bv || (ov == bv && oi < bi)) { bv = ov; bi = oi; }
        }
        if (t == 0) {
            g_lse[row]  = lse;
            g_pred[row] = bi;
            atomicAdd(&g_cnt[bi], 1);
        }
    }

#pragma unroll
    for (int o = 16; o > 0; o >>= 1) entL += __shfl_xor_sync(0xffffffffu, entL, o);
    if (lane == 0) atomicAdd(&g_ent, entL);

#pragma unroll
    for (int o = 4; o <= 16; o <<= 1)
#pragma unroll
        for (int nt = 0; nt < 10; nt++)
#pragma unroll
            for (int j = 0; j < 2; j++)
                su[nt][j] += __shfl_xor_sync(0xffffffffu, su[nt][j], o);
    if (g == 0) {
#pragma unroll
        for (int nt = 0; nt < 10; nt++)
#pragma unroll
            for (int j = 0; j < 2; j++) {
                int col = nt * 8 + 2 * t + j;
                if (col < CDIM) atomicAdd(&g_sump[col], su[nt][j]);
            }
    }
}

// ---- scan: exclusive prefix of g_cnt -> g_fill, g_start ----
__global__ void scan_kernel()
{
    if (threadIdx.x == 0) {
        int acc = 0;
        for (int c = 0; c < CDIM; c++) {
            g_fill[c]  = acc;
            g_start[c] = acc;
            acc += g_cnt[c];
        }
        g_start[CDIM] = acc;
    }
}

// ---- scatter: counting-sort rows by class into g_perm ----
__global__ void __launch_bounds__(256) scatter_kernel()
{
    int i = blockIdx.x * 256 + threadIdx.x;
    if (i < NROWS) {
        int c = g_pred[i];
        int pos = atomicAdd(&g_fill[c], 1);
        g_perm[pos] = i;
    }
}

// ---- segsum per class: block (colslab, c) owns class c / 256 columns.
//      Register accumulation, 8-wide independent load batches, plain stores.
#define SEGC_CHUNK 256
__global__ void __launch_bounds__(128) segsum_class()
{
    __shared__ int sperm[SEGC_CHUNK];
    const int c    = blockIdx.y;
    const int t    = threadIdx.x;
    const int col2 = blockIdx.x * 128 + t;          // half2 column
    const int start = g_start[c];
    const int end   = g_start[c + 1];

    const unsigned* f2 = reinterpret_cast<const unsigned*>(g_feat16);
    float rx = 0.f, ry = 0.f;

    for (int base = start; base < end; base += SEGC_CHUNK) {
        int n = min(SEGC_CHUNK, end - base);
        __syncthreads();
        for (int i = t; i < n; i += 128) sperm[i] = g_perm[base + i];
        __syncthreads();

        int i = 0;
        for (; i + 8 <= n; i += 8) {
            unsigned u[8];
#pragma unroll
            for (int j = 0; j < 8; j++)
                u[j] = f2[(size_t)sperm[i + j] * (DDIM / 2) + col2];
#pragma unroll
            for (int j = 0; j < 8; j++) {
                float2 v = __half22float2(*reinterpret_cast<__half2*>(&u[j]));
                rx += v.x; ry += v.y;
            }
        }
        for (; i < n; i++) {
            unsigned u = f2[(size_t)sperm[i] * (DDIM / 2) + col2];
            float2 v = __half22float2(*reinterpret_cast<__half2*>(&u));
            rx += v.x; ry += v.y;
        }
    }
    g_csum[c * DDIM + 2 * col2]     = rx;
    g_csum[c * DDIM + 2 * col2 + 1] = ry;
}

// ---- finalize centroids (normalized), K-major fp16; grid = 96 ----
__global__ void __launch_bounds__(256) centroid_f16()
{
    __shared__ float red[256];
    const int c = blockIdx.x;
    const int t = threadIdx.x;
    if (c >= CDIM) {
        for (int d = t; d < DDIM; d += 256) g_cent16[(size_t)c * DDIM + d] = __float2half_rn(0.f);
        return;
    }
    const int cnt = g_cnt[c];
    const float denom = fmaxf((float)cnt, 1.f);

    float ssq = 0.f;
    for (int d = t; d < DDIM; d += 256) {
        float mv = g_csum[c * DDIM + d] / denom;
        ssq += mv * mv;
    }
    red[t] = ssq;
    __syncthreads();
    for (int o = 128; o > 0; o >>= 1) { if (t < o) red[t] += red[t + o]; __syncthreads(); }
    float nrm   = sqrtf(red[0]);
    float scale = (cnt > 0) ? 1.f / (denom * fmaxf(nrm, 1e-12f)) : 0.f;

    for (int d = t; d < DDIM; d += 256)
        g_cent16[(size_t)c * DDIM + d] = __float2half_rn(g_csum[c * DDIM + d] * scale);
}

// ---- sim (fp16, 2-stage): A = g_feat16, B = g_cent16 ; fused argmax + CE ----
__global__ void __launch_bounds__(256) sim_f16()
{
    extern __shared__ __align__(1024) char dsm[];
    const unsigned sbase = smem_u32(dsm);
    const int tid  = threadIdx.x;
    const int lane = tid & 31;
    const int w    = tid >> 5;
    const int t    = lane & 3;
    const int row0 = blockIdx.x * 128;
    const int cr   = tid >> 3;
    const int cc   = tid & 7;

    auto issue_copy = [&](int kt) {
        const unsigned aoff = (kt & 1) * 28672u;
        const unsigned boff = aoff + 16384u;
        const __half* Ag = &g_feat16[(size_t)row0 * DDIM + kt * 64];
        const __half* Bg = &g_cent16[kt * 64];
#pragma unroll
        for (int i = 0; i < 4; i++) {
            int r = cr + 32 * i;
            unsigned dsw = (unsigned)((cc ^ (r & 7)) << 4);
            CP_ASYNC16(sbase + aoff + r * 128 + dsw, Ag + (size_t)r * DDIM + cc * 8);
        }
#pragma unroll
        for (int i = 0; i < 3; i++) {
            int q = tid + 256 * i;
            int r = q >> 3, c = q & 7;
            unsigned dsw = (unsigned)((c ^ (r & 7)) << 4);
            CP_ASYNC16(sbase + boff + r * 128 + dsw, Bg + (size_t)r * DDIM + c * 8);
        }
        CP_COMMIT();
    };

    float acc[10][4];
#pragma unroll
    for (int n = 0; n < 10; n++)
#pragma unroll
        for (int c = 0; c < 4; c++) acc[n][c] = 0.f;

    issue_copy(0);
    const int NT = DDIM / 64;   // 32
    for (int kt = 0; kt < NT; kt++) {
        if (kt + 1 < NT) { issue_copy(kt + 1); CP_WAIT(1); }
        else             { CP_WAIT(0); }
        __syncthreads();

        const unsigned aoff = (kt & 1) * 28672u;
        const unsigned boff = aoff + 16384u;
        const int arl = lane & 15;
        const int ach = lane >> 4;

#pragma unroll
        for (int ks = 0; ks < 4; ks++) {
            unsigned b0[12], b1[12];
#pragma unroll
            for (int gr = 0; gr < 3; gr++) {
                int bn = gr * 32 + lane;
                unsigned bline = sbase + boff + bn * 128;
                int c0 = (2 * ks) ^ (bn & 7);
                int c1 = (2 * ks + 1) ^ (bn & 7);
                ldsm_x4(b0[gr*4+0], b0[gr*4+1], b0[gr*4+2], b0[gr*4+3], bline + (c0 << 4));
                ldsm_x4(b1[gr*4+0], b1[gr*4+1], b1[gr*4+2], b1[gr*4+3], bline + (c1 << 4));
            }
            int row = w * 16 + arl;
            int ch  = (2 * ks + ach) ^ (row & 7);
            unsigned a0, a1, a2, a3;
            ldsm_x4(a0, a1, a2, a3, sbase + aoff + row * 128 + (ch << 4));
#pragma unroll
            for (int nt = 0; nt < 10; nt++)
                mma_f16(acc[nt], a0, a1, a2, a3, b0[nt], b1[nt]);
        }
        __syncthreads();
    }

    const int g = lane >> 2;
    float ceL = 0.f;
#pragma unroll
    for (int half = 0; half < 2; half++) {
        int row = row0 + w * 16 + g + 8 * half;
        int ci  = 2 * half;

        float bv = -1e30f; int bi = CDIM;
#pragma unroll
        for (int nt = 0; nt < 10; nt++)
#pragma unroll
            for (int j = 0; j < 2; j++) {
                int col = nt * 8 + 2 * t + j;
                if (col < CDIM) {
                    float vv = acc[nt][ci + j];
                    if (vv > bv || (vv == bv && col < bi)) { bv = vv; bi = col; }
                }
            }
#pragma unroll
        for (int o = 1; o <= 2; o <<= 1) {
            float ov = __shfl_xor_sync(0xffffffffu, bv, o);
            int   oi = __shfl_xor_sync(0xffffffffu, bi, o);
            if (ov > bv || (ov == bv && oi < bi)) { bv = ov; bi = oi; }
        }
        if (t == 0)
            ceL += g_lse[row] - g_logits[row * CDIM + bi];
    }
#pragma unroll
    for (int o = 16; o > 0; o >>= 1) ceL += __shfl_xor_sync(0xffffffffu, ceL, o);
    if (lane == 0) atomicAdd(&g_ce, ceL);
}

// ---------------- final scalar ----------------
__global__ void finalize_kernel(float* __restrict__ out)
{
    __shared__ float red[128];
    int t = threadIdx.x;
    float v = 0.f;
    if (t < CDIM) {
        float mp = g_sump[t] * (1.f / NROWS);
        v = mp * logf(mp + 1e-6f);
    }
    red[t] = v;
    __syncthreads();
    for (int o = 64; o > 0; o >>= 1) { if (t < o) red[t] += red[t + o]; __syncthreads(); }
    if (t == 0) {
        float entropy = -g_ent * (1.f / NROWS);
        float ce      =  g_ce  * (1.f / NROWS);
        out[0] = entropy + red[0] + 0.3f * ce;
    }
}

// ---------------- launch ----------------
extern "C" void kernel_launch(void* const* d_in, const int* in_sizes, int n_in,
                              void* d_out, int out_size)
{
    const float* feat = (const float*)d_in[0];
    const float* w1   = (const float*)d_in[1];
    const float* b1   = (const float*)d_in[2];
    const float* w2   = (const float*)d_in[3];
    const float* b2   = (const float*)d_in[4];
    float* out = (float*)d_out;

    cudaFuncSetAttribute(gemm1_fp16, cudaFuncAttributeMaxDynamicSharedMemorySize, G1_SMEM);
    cudaFuncSetAttribute(logits_f16, cudaFuncAttributeMaxDynamicSharedMemorySize, SK_SMEM);
    cudaFuncSetAttribute(sim_f16,    cudaFuncAttributeMaxDynamicSharedMemorySize, SK_SMEM);

    prep_kernel<<<PREP_BLOCKS, 256>>>(feat, w1, w2);
    gemm1_fp16<<<dim3(HDIM / 128, NROWS / 128), 256, G1_SMEM>>>(b1);
    logits_f16<<<NROWS / 128, 256, SK_SMEM>>>(b2);
    scan_kernel<<<1, 32>>>();
    scatter_kernel<<<NROWS / 256, 256>>>();
    segsum_class<<<dim3(DDIM / 256, CDIM), 128>>>();
    centroid_f16<<<BPADR, 256>>>();
    sim_f16<<<NROWS / 128, 256, SK_SMEM>>>();
    finalize_kernel<<<1, 128>>>(out);
}

// round 12
// speedup vs baseline: 1.3381x; 1.2705x over previous
#include <cuda_runtime.h>
#include <cuda_fp16.h>
#include <math.h>
#include <stdint.h>

#define NROWS 16384
#define DDIM  2048
#define HDIM  512
#define CDIM  65
#define KPAIRS (DDIM / 2)
#define BPADR 96     // padded B rows for ldmatrix groups of 32

// ---------------- scratch (device globals; no allocation) ----------------
__device__ __half        g_h16[NROWS * HDIM];      // post-dropout hidden (fp16)
__device__ __half        g_feat16[NROWS * DDIM];   // feat converted to fp16
__device__ float         g_logits[NROWS * CDIM];
__device__ float         g_lse[NROWS];
__device__ int           g_pred[NROWS];
__device__ float         g_sump[CDIM];
__device__ float         g_ent;
__device__ float         g_ce;
__device__ float         g_csum[CDIM * DDIM];
__device__ int           g_cnt[CDIM];
__device__ int           g_fill[CDIM];             // scatter cursors (zeroed)
__device__ int           g_perm[NROWS];            // rows sorted by class
__device__ unsigned      g_w1Th[HDIM * KPAIRS];    // half2 pairs, [n][k]
__device__ __half        g_w2T16[BPADR * HDIM];    // [n][k] fp16, rows>=CDIM zero
__device__ __half        g_cent16[BPADR * DDIM];   // [c][d] fp16 centroids

// ---------------- helpers ----------------
__device__ __forceinline__ unsigned pack_h2(float a, float b)
{
    __half2 h = __floats2half2_rn(a, b);
    return *reinterpret_cast<unsigned*>(&h);
}

__device__ __forceinline__ unsigned smem_u32(const void* p)
{
    unsigned a;
    asm("{ .reg .u64 t; cvta.to.shared.u64 t, %1; cvt.u32.u64 %0, t; }" : "=r"(a) : "l"(p));
    return a;
}

__device__ __forceinline__ void mma_f16(float c[4],
                                        unsigned a0, unsigned a1, unsigned a2, unsigned a3,
                                        unsigned b0, unsigned b1)
{
    asm volatile(
        "mma.sync.aligned.m16n8k16.row.col.f32.f16.f16.f32 "
        "{%0,%1,%2,%3}, {%4,%5,%6,%7}, {%8,%9}, {%0,%1,%2,%3};"
        : "+f"(c[0]), "+f"(c[1]), "+f"(c[2]), "+f"(c[3])
        : "r"(a0), "r"(a1), "r"(a2), "r"(a3), "r"(b0), "r"(b1));
}

__device__ __forceinline__ void ldsm_x4(unsigned& r0, unsigned& r1, unsigned& r2, unsigned& r3,
                                        unsigned saddr)
{
    asm volatile("ldmatrix.sync.aligned.m8n8.x4.shared.b16 {%0,%1,%2,%3}, [%4];"
                 : "=r"(r0), "=r"(r1), "=r"(r2), "=r"(r3) : "r"(saddr));
}

#define CP_ASYNC16(dst, src) \
    asm volatile("cp.async.cg.shared.global [%0], [%1], 16;" :: "r"(dst), "l"(src))
#define CP_COMMIT() asm volatile("cp.async.commit_group;")
#define CP_WAIT(n)  asm volatile("cp.async.wait_group %0;" :: "n"(n))

// ---------------- threefry2x32 (JAX partitionable, key = (0, 42)) ----------------
__device__ __forceinline__ void threefry2x32_42(unsigned c0, unsigned c1,
                                                unsigned& o0, unsigned& o1)
{
    const unsigned ks0 = 0u;
    const unsigned ks1 = 42u;
    const unsigned ks2 = 0x1BD11BDAu ^ 0u ^ 42u;
    unsigned x0 = c0 + ks0;
    unsigned x1 = c1 + ks1;
#define TF_ROUND(r) { x0 += x1; x1 = (x1 << (r)) | (x1 >> (32 - (r))); x1 ^= x0; }
    TF_ROUND(13) TF_ROUND(15) TF_ROUND(26) TF_ROUND(6)
    x0 += ks1; x1 += ks2 + 1u;
    TF_ROUND(17) TF_ROUND(29) TF_ROUND(16) TF_ROUND(24)
    x0 += ks2; x1 += ks0 + 2u;
    TF_ROUND(13) TF_ROUND(15) TF_ROUND(26) TF_ROUND(6)
    x0 += ks0; x1 += ks1 + 3u;
    TF_ROUND(17) TF_ROUND(29) TF_ROUND(16) TF_ROUND(24)
    x0 += ks1; x1 += ks2 + 4u;
    TF_ROUND(13) TF_ROUND(15) TF_ROUND(26) TF_ROUND(6)
    x0 += ks2; x1 += ks0 + 5u;
#undef TF_ROUND
    o0 = x0; o1 = x1;
}

__device__ __forceinline__ bool keep_bit(unsigned idx)
{
    unsigned a, b;
    threefry2x32_42(0u, idx, a, b);
    return (b >> 31) == 0u;
}

// ============================================================================
// prep: feat->fp16, w1 transpose->fp16, w2 transpose->fp16, zero accumulators
// ============================================================================
#define FEAT_BLOCKS (NROWS * DDIM / (256 * 8))          // 16384
#define W1T_BLOCKS  ((DDIM / 32) * (HDIM / 32))         // 1024
#define W2T_BLOCKS  ((BPADR * HDIM + 255) / 256)        // 192
#define ZERO_BLOCKS ((CDIM * DDIM + 255) / 256)         // 520
#define PREP_BLOCKS (FEAT_BLOCKS + W1T_BLOCKS + W2T_BLOCKS + ZERO_BLOCKS)

__global__ void __launch_bounds__(256) prep_kernel(const float* __restrict__ feat,
                                                   const float* __restrict__ w1,
                                                   const float* __restrict__ w2)
{
    __shared__ float t[32][33];
    const int b = blockIdx.x;
    const int tid = threadIdx.x;

    if (b < FEAT_BLOCKS) {
        size_t i = ((size_t)b * 256 + tid) * 8;
        float4 v0 = *reinterpret_cast<const float4*>(feat + i);
        float4 v1 = *reinterpret_cast<const float4*>(feat + i + 4);
        uint4 o;
        o.x = pack_h2(v0.x, v0.y);
        o.y = pack_h2(v0.z, v0.w);
        o.z = pack_h2(v1.x, v1.y);
        o.w = pack_h2(v1.z, v1.w);
        *reinterpret_cast<uint4*>(&g_feat16[i]) = o;
    } else if (b < FEAT_BLOCKS + W1T_BLOCKS) {
        int q = b - FEAT_BLOCKS;
        int k0 = (q & 63) * 32, n0 = (q >> 6) * 32;
        int x = tid & 31, y = tid >> 5;
#pragma unroll
        for (int i = y; i < 32; i += 8) t[i][x] = w1[(size_t)(k0 + i) * HDIM + n0 + x];
        __syncthreads();
#pragma unroll
        for (int i = y; i < 16; i += 8)
            g_w1Th[(size_t)(n0 + x) * KPAIRS + k0 / 2 + i] = pack_h2(t[2 * i][x], t[2 * i + 1][x]);
    } else if (b < FEAT_BLOCKS + W1T_BLOCKS + W2T_BLOCKS) {
        int i = (b - FEAT_BLOCKS - W1T_BLOCKS) * 256 + tid;
        if (i < BPADR * HDIM) {
            int n = i / HDIM, k = i - n * HDIM;
            g_w2T16[i] = (n < CDIM) ? __float2half_rn(w2[k * CDIM + n]) : __float2half_rn(0.f);
        }
    } else {
        int i = (b - FEAT_BLOCKS - W1T_BLOCKS - W2T_BLOCKS) * 256 + tid;
        if (i < CDIM * DDIM) g_csum[i] = 0.f;
        if (i < CDIM) { g_sump[i] = 0.f; g_cnt[i] = 0; g_fill[i] = 0; }
        if (i == 0) { g_ent = 0.f; g_ce = 0.f; }
    }
}

// ============================================================================
// GEMM1 (fp16, 2-stage cp.async + ldmatrix): g_h16 = dropout(relu(feat@w1+b1))
// ============================================================================
#define G1_SMEM (2 * 32768)

__global__ void __launch_bounds__(256) gemm1_fp16(const float* __restrict__ bias)
{
    extern __shared__ __align__(1024) char dsm[];
    __shared__ float sb[128];

    const unsigned sbase = smem_u32(dsm);
    const int tid  = threadIdx.x;
    const int lane = tid & 31;
    const int w    = tid >> 5;
    const int g    = lane >> 2;
    const int t    = lane & 3;
    const int wm   = w & 1;
    const int wn   = w >> 1;
    const int brow = blockIdx.y * 128;
    const int bcol = blockIdx.x * 128;

    if (tid < 128) sb[tid] = bias[bcol + tid];

    const int NT = DDIM / 64;           // 32
    const int cr = tid >> 3;
    const int cc = tid & 7;

    auto issue_copy = [&](int kt) {
        const unsigned aoff = (kt & 1) * 32768u;
        const unsigned boff = aoff + 16384u;
        const __half* Ag = &g_feat16[(size_t)brow * DDIM + kt * 64];
        const unsigned* Bg = &g_w1Th[(size_t)bcol * KPAIRS + kt * 32];
#pragma unroll
        for (int i = 0; i < 4; i++) {
            int r = cr + 32 * i;
            unsigned dsw = (unsigned)((cc ^ (r & 7)) << 4);
            CP_ASYNC16(sbase + aoff + r * 128 + dsw, Ag + (size_t)r * DDIM + cc * 8);
            CP_ASYNC16(sbase + boff + r * 128 + dsw, Bg + (size_t)r * KPAIRS + cc * 4);
        }
        CP_COMMIT();
    };

    float acc[4][4][4];
#pragma unroll
    for (int i = 0; i < 4; i++)
#pragma unroll
        for (int j = 0; j < 4; j++)
#pragma unroll
            for (int c = 0; c < 4; c++) acc[i][j][c] = 0.f;

    issue_copy(0);

    for (int kt = 0; kt < NT; kt++) {
        if (kt + 1 < NT) { issue_copy(kt + 1); CP_WAIT(1); }
        else             { CP_WAIT(0); }
        __syncthreads();

        const unsigned aoff = (kt & 1) * 32768u;
        const unsigned boff = aoff + 16384u;

        const int bn = wn * 32 + lane;
        const unsigned bline = sbase + boff + bn * 128;
        const int arl = (lane & 15);
        const int ach = (lane >> 4);

#pragma unroll
        for (int ks = 0; ks < 4; ks++) {
            unsigned b0[4], b1[4];
            {
                int c0 = (2 * ks) ^ (bn & 7);
                int c1 = (2 * ks + 1) ^ (bn & 7);
                ldsm_x4(b0[0], b0[1], b0[2], b0[3], bline + (c0 << 4));
                ldsm_x4(b1[0], b1[1], b1[2], b1[3], bline + (c1 << 4));
            }
#pragma unroll
            for (int mt = 0; mt < 4; mt++) {
                int row = wm * 64 + mt * 16 + arl;
                int ch  = (2 * ks + ach) ^ (row & 7);
                unsigned a0, a1, a2, a3;
                ldsm_x4(a0, a1, a2, a3, sbase + aoff + row * 128 + (ch << 4));
#pragma unroll
                for (int nt = 0; nt < 4; nt++)
                    mma_f16(acc[mt][nt], a0, a1, a2, a3, b0[nt], b1[nt]);
            }
        }
        __syncthreads();
    }

#pragma unroll
    for (int mt = 0; mt < 4; mt++) {
#pragma unroll
        for (int h = 0; h < 2; h++) {
            int row = brow + wm * 64 + mt * 16 + g + 8 * h;
#pragma unroll
            for (int nt = 0; nt < 4; nt++) {
                int colL = wn * 32 + nt * 8 + 2 * t;
                unsigned i0 = (unsigned)(row * HDIM + bcol + colL);
                float v0 = fmaxf(acc[mt][nt][2 * h + 0] + sb[colL], 0.f);
                float v1 = fmaxf(acc[mt][nt][2 * h + 1] + sb[colL + 1], 0.f);
                unsigned o = pack_h2(keep_bit(i0)     ? (v0 + v0) : 0.f,
                                     keep_bit(i0 + 1) ? (v1 + v1) : 0.f);
                *reinterpret_cast<unsigned*>(&g_h16[i0]) = o;
            }
        }
    }
}

// ============================================================================
// logits (fp16, 2-stage): A = g_h16, B = g_w2T16; fused stats/argmax/counts.
// ============================================================================
#define SK_SMEM 57344

__global__ void __launch_bounds__(256) logits_f16(const float* __restrict__ b2)
{
    extern __shared__ __align__(1024) char dsm[];
    const unsigned sbase = smem_u32(dsm);
    const int tid  = threadIdx.x;
    const int lane = tid & 31;
    const int w    = tid >> 5;
    const int g    = lane >> 2;
    const int t    = lane & 3;
    const int row0 = blockIdx.x * 128;
    const int cr   = tid >> 3;
    const int cc   = tid & 7;

    auto issue_copy = [&](int kt) {
        const unsigned aoff = (kt & 1) * 28672u;
        const unsigned boff = aoff + 16384u;
        const __half* Ag = &g_h16[(size_t)row0 * HDIM + kt * 64];
        const __half* Bg = &g_w2T16[kt * 64];
#pragma unroll
        for (int i = 0; i < 4; i++) {
            int r = cr + 32 * i;
            unsigned dsw = (unsigned)((cc ^ (r & 7)) << 4);
            CP_ASYNC16(sbase + aoff + r * 128 + dsw, Ag + (size_t)r * HDIM + cc * 8);
        }
#pragma unroll
        for (int i = 0; i < 3; i++) {
            int q = tid + 256 * i;
            int r = q >> 3, c = q & 7;
            unsigned dsw = (unsigned)((c ^ (r & 7)) << 4);
            CP_ASYNC16(sbase + boff + r * 128 + dsw, Bg + (size_t)r * HDIM + c * 8);
        }
        CP_COMMIT();
    };

    float acc[10][4];
#pragma unroll
    for (int n = 0; n < 10; n++)
#pragma unroll
        for (int c = 0; c < 4; c++) acc[n][c] = 0.f;

    issue_copy(0);
    const int NT = HDIM / 64;   // 8
    for (int kt = 0; kt < NT; kt++) {
        if (kt + 1 < NT) { issue_copy(kt + 1); CP_WAIT(1); }
        else             { CP_WAIT(0); }
        __syncthreads();

        const unsigned aoff = (kt & 1) * 28672u;
        const unsigned boff = aoff + 16384u;
        const int arl = lane & 15;
        const int ach = lane >> 4;

#pragma unroll
        for (int ks = 0; ks < 4; ks++) {
            unsigned b0[12], b1[12];
#pragma unroll
            for (int gr = 0; gr < 3; gr++) {
                int bn = gr * 32 + lane;
                unsigned bline = sbase + boff + bn * 128;
                int c0 = (2 * ks) ^ (bn & 7);
                int c1 = (2 * ks + 1) ^ (bn & 7);
                ldsm_x4(b0[gr*4+0], b0[gr*4+1], b0[gr*4+2], b0[gr*4+3], bline + (c0 << 4));
                ldsm_x4(b1[gr*4+0], b1[gr*4+1], b1[gr*4+2], b1[gr*4+3], bline + (c1 << 4));
            }
            int row = w * 16 + arl;
            int ch  = (2 * ks + ach) ^ (row & 7);
            unsigned a0, a1, a2, a3;
            ldsm_x4(a0, a1, a2, a3, sbase + aoff + row * 128 + (ch << 4));
#pragma unroll
            for (int nt = 0; nt < 10; nt++)
                mma_f16(acc[nt], a0, a1, a2, a3, b0[nt], b1[nt]);
        }
        __syncthreads();
    }

    float su[10][2];
#pragma unroll
    for (int n = 0; n < 10; n++) { su[n][0] = 0.f; su[n][1] = 0.f; }
    float entL = 0.f;

#pragma unroll
    for (int half = 0; half < 2; half++) {
        int row = row0 + w * 16 + g + 8 * half;
        int ci  = 2 * half;

        float v[10][2];
        float m = -1e30f;
#pragma unroll
        for (int nt = 0; nt < 10; nt++)
#pragma unroll
            for (int j = 0; j < 2; j++) {
                int col = nt * 8 + 2 * t + j;
                v[nt][j] = (col < CDIM) ? acc[nt][ci + j] + b2[col] : -1e30f;
                m = fmaxf(m, v[nt][j]);
            }
        m = fmaxf(m, __shfl_xor_sync(0xffffffffu, m, 1));
        m = fmaxf(m, __shfl_xor_sync(0xffffffffu, m, 2));

        float s = 0.f;
#pragma unroll
        for (int nt = 0; nt < 10; nt++)
#pragma unroll
            for (int j = 0; j < 2; j++) {
                int col = nt * 8 + 2 * t + j;
                if (col < CDIM) s += expf(v[nt][j] - m);
            }
        s += __shfl_xor_sync(0xffffffffu, s, 1);
        s += __shfl_xor_sync(0xffffffffu, s, 2);
        float lse = m + logf(s);

        float bv = -1e30f; int bi = CDIM;
#pragma unroll
        for (int nt = 0; nt < 10; nt++)
#pragma unroll
            for (int j = 0; j < 2; j++) {
                int col = nt * 8 + 2 * t + j;
                if (col < CDIM) {
                    float p = expf(v[nt][j] - lse);
                    entL += p * logf(p + 1e-6f);
                    su[nt][j] += p;
                    g_logits[row * CDIM + col] = v[nt][j];
                    if (v[nt][j] > bv || (v[nt][j] == bv && col < bi)) { bv = v[nt][j]; bi = col; }
                }
            }
#pragma unroll
        for (int o = 1; o <= 2; o <<= 1) {
            float ov = __shfl_xor_sync(0xffffffffu, bv, o);
            int   oi = __shfl_xor_sync(0xffffffffu, bi, o);
            if (ov > bv || (ov == bv && oi < bi)) { bv = ov; bi = oi; }
        }
        if (t == 0) {
            g_lse[row]  = lse;
            g_pred[row] = bi;
            atomicAdd(&g_cnt[bi], 1);
        }
    }

#pragma unroll
    for (int o = 16; o > 0; o >>= 1) entL += __shfl_xor_sync(0xffffffffu, entL, o);
    if (lane == 0) atomicAdd(&g_ent, entL);

#pragma unroll
    for (int o = 4; o <= 16; o <<= 1)
#pragma unroll
        for (int nt = 0; nt < 10; nt++)
#pragma unroll
            for (int j = 0; j < 2; j++)
                su[nt][j] += __shfl_xor_sync(0xffffffffu, su[nt][j], o);
    if (g == 0) {
#pragma unroll
        for (int nt = 0; nt < 10; nt++)
#pragma unroll
            for (int j = 0; j < 2; j++) {
                int col = nt * 8 + 2 * t + j;
                if (col < CDIM) atomicAdd(&g_sump[col], su[nt][j]);
            }
    }
}

// ---- scatter: counting-sort rows by class into g_perm.
//      Each block computes the class prefix locally (no separate scan kernel).
__global__ void __launch_bounds__(256) scatter_kernel()
{
    __shared__ int sstart[CDIM];
    if (threadIdx.x == 0) {
        int acc = 0;
        for (int c = 0; c < CDIM; c++) { sstart[c] = acc; acc += g_cnt[c]; }
    }
    __syncthreads();
    int i = blockIdx.x * 256 + threadIdx.x;
    if (i < NROWS) {
        int c = g_pred[i];
        int pos = sstart[c] + atomicAdd(&g_fill[c], 1);
        g_perm[pos] = i;
    }
}

// ---- segsum over fixed 256-row chunks of sorted order:
//      register run accumulation, 8-wide double-buffered batches, boundary atomics.
#define SEG_CHUNK 256
__global__ void __launch_bounds__(128) segsum_sorted()
{
    __shared__ int sperm[SEG_CHUNK];
    __shared__ int scls[SEG_CHUNK];

    const int t    = threadIdx.x;
    const int col2 = blockIdx.x * 128 + t;          // half2 column
    const int r0   = blockIdx.y * SEG_CHUNK;

    for (int i = t; i < SEG_CHUNK; i += 128) {
        int p = g_perm[r0 + i];
        sperm[i] = p;
        scls[i]  = g_pred[p];
    }
    __syncthreads();

    const unsigned* f2 = reinterpret_cast<const unsigned*>(g_feat16);
    float rx = 0.f, ry = 0.f;
    int cur = scls[0];

    unsigned buf[8];
#pragma unroll
    for (int j = 0; j < 8; j++)
        buf[j] = f2[(size_t)sperm[j] * (DDIM / 2) + col2];

    for (int base = 0; base < SEG_CHUNK; base += 8) {
        unsigned nbuf[8];
        if (base + 8 < SEG_CHUNK) {
#pragma unroll
            for (int j = 0; j < 8; j++)
                nbuf[j] = f2[(size_t)sperm[base + 8 + j] * (DDIM / 2) + col2];
        }
#pragma unroll
        for (int j = 0; j < 8; j++) {
            int c = scls[base + j];
            if (c != cur) {
                atomicAdd(&g_csum[cur * DDIM + 2 * col2],     rx);
                atomicAdd(&g_csum[cur * DDIM + 2 * col2 + 1], ry);
                rx = 0.f; ry = 0.f; cur = c;
            }
            float2 v = __half22float2(*reinterpret_cast<__half2*>(&buf[j]));
            rx += v.x; ry += v.y;
        }
#pragma unroll
        for (int j = 0; j < 8; j++) buf[j] = nbuf[j];
    }
    atomicAdd(&g_csum[cur * DDIM + 2 * col2],     rx);
    atomicAdd(&g_csum[cur * DDIM + 2 * col2 + 1], ry);
}

// ---- finalize centroids (normalized), K-major fp16; grid = 96 ----
__global__ void __launch_bounds__(256) centroid_f16()
{
    __shared__ float red[256];
    const int c = blockIdx.x;
    const int t = threadIdx.x;
    if (c >= CDIM) {
        for (int d = t; d < DDIM; d += 256) g_cent16[(size_t)c * DDIM + d] = __float2half_rn(0.f);
        return;
    }
    const int cnt = g_cnt[c];
    const float denom = fmaxf((float)cnt, 1.f);

    float ssq = 0.f;
    for (int d = t; d < DDIM; d += 256) {
        float mv = g_csum[c * DDIM + d] / denom;
        ssq += mv * mv;
    }
    red[t] = ssq;
    __syncthreads();
    for (int o = 128; o > 0; o >>= 1) { if (t < o) red[t] += red[t + o]; __syncthreads(); }
    float nrm   = sqrtf(red[0]);
    float scale = (cnt > 0) ? 1.f / (denom * fmaxf(nrm, 1e-12f)) : 0.f;

    for (int d = t; d < DDIM; d += 256)
        g_cent16[(size_t)c * DDIM + d] = __float2half_rn(g_csum[c * DDIM + d] * scale);
}

// ---- sim (fp16, 2-stage): A = g_feat16, B = g_cent16 ; fused argmax + CE ----
__global__ void __launch_bounds__(256) sim_f16()
{
    extern __shared__ __align__(1024) char dsm[];
    const unsigned sbase = smem_u32(dsm);
    const int tid  = threadIdx.x;
    const int lane = tid & 31;
    const int w    = tid >> 5;
    const int t    = lane & 3;
    const int row0 = blockIdx.x * 128;
    const int cr   = tid >> 3;
    const int cc   = tid & 7;

    auto issue_copy = [&](int kt) {
        const unsigned aoff = (kt & 1) * 28672u;
        const unsigned boff = aoff + 16384u;
        const __half* Ag = &g_feat16[(size_t)row0 * DDIM + kt * 64];
        const __half* Bg = &g_cent16[kt * 64];
#pragma unroll
        for (int i = 0; i < 4; i++) {
            int r = cr + 32 * i;
            unsigned dsw = (unsigned)((cc ^ (r & 7)) << 4);
            CP_ASYNC16(sbase + aoff + r * 128 + dsw, Ag + (size_t)r * DDIM + cc * 8);
        }
#pragma unroll
        for (int i = 0; i < 3; i++) {
            int q = tid + 256 * i;
            int r = q >> 3, c = q & 7;
            unsigned dsw = (unsigned)((c ^ (r & 7)) << 4);
            CP_ASYNC16(sbase + boff + r * 128 + dsw, Bg + (size_t)r * DDIM + c * 8);
        }
        CP_COMMIT();
    };

    float acc[10][4];
#pragma unroll
    for (int n = 0; n < 10; n++)
#pragma unroll
        for (int c = 0; c < 4; c++) acc[n][c] = 0.f;

    issue_copy(0);
    const int NT = DDIM / 64;   // 32
    for (int kt = 0; kt < NT; kt++) {
        if (kt + 1 < NT) { issue_copy(kt + 1); CP_WAIT(1); }
        else             { CP_WAIT(0); }
        __syncthreads();

        const unsigned aoff = (kt & 1) * 28672u;
        const unsigned boff = aoff + 16384u;
        const int arl = lane & 15;
        const int ach = lane >> 4;

#pragma unroll
        for (int ks = 0; ks < 4; ks++) {
            unsigned b0[12], b1[12];
#pragma unroll
            for (int gr = 0; gr < 3; gr++) {
                int bn = gr * 32 + lane;
                unsigned bline = sbase + boff + bn * 128;
                int c0 = (2 * ks) ^ (bn & 7);
                int c1 = (2 * ks + 1) ^ (bn & 7);
                ldsm_x4(b0[gr*4+0], b0[gr*4+1], b0[gr*4+2], b0[gr*4+3], bline + (c0 << 4));
                ldsm_x4(b1[gr*4+0], b1[gr*4+1], b1[gr*4+2], b1[gr*4+3], bline + (c1 << 4));
            }
            int row = w * 16 + arl;
            int ch  = (2 * ks + ach) ^ (row & 7);
            unsigned a0, a1, a2, a3;
            ldsm_x4(a0, a1, a2, a3, sbase + aoff + row * 128 + (ch << 4));
#pragma unroll
            for (int nt = 0; nt < 10; nt++)
                mma_f16(acc[nt], a0, a1, a2, a3, b0[nt], b1[nt]);
        }
        __syncthreads();
    }

    const int g = lane >> 2;
    float ceL = 0.f;
#pragma unroll
    for (int half = 0; half < 2; half++) {
        int row = row0 + w * 16 + g + 8 * half;
        int ci  = 2 * half;

        float bv = -1e30f; int bi = CDIM;
#pragma unroll
        for (int nt = 0; nt < 10; nt++)
#pragma unroll
            for (int j = 0; j < 2; j++) {
                int col = nt * 8 + 2 * t + j;
                if (col < CDIM) {
                    float vv = acc[nt][ci + j];
                    if (vv > bv || (vv == bv && col < bi)) { bv = vv; bi = col; }
                }
            }
#pragma unroll
        for (int o = 1; o <= 2; o <<= 1) {
            float ov = __shfl_xor_sync(0xffffffffu, bv, o);
            int   oi = __shfl_xor_sync(0xffffffffu, bi, o);
            if (ov > bv || (ov == bv && oi < bi)) { bv = ov; bi = oi; }
        }
        if (t == 0)
            ceL += g_lse[row] - g_logits[row * CDIM + bi];
    }
#pragma unroll
    for (int o = 16; o > 0; o >>= 1) ceL += __shfl_xor_sync(0xffffffffu, ceL, o);
    if (lane == 0) atomicAdd(&g_ce, ceL);
}

// ---------------- final scalar ----------------
__global__ void finalize_kernel(float* __restrict__ out)
{
    __shared__ float red[128];
    int t = threadIdx.x;
    float v = 0.f;
    if (t < CDIM) {
        float mp = g_sump[t] * (1.f / NROWS);
        v = mp * logf(mp + 1e-6f);
    }
    red[t] = v;
    __syncthreads();
    for (int o = 64; o > 0; o >>= 1) { if (t < o) red[t] += red[t + o]; __syncthreads(); }
    if (t == 0) {
        float entropy = -g_ent * (1.f / NROWS);
        float ce      =  g_ce  * (1.f / NROWS);
        out[0] = entropy + red[0] + 0.3f * ce;
    }
}

// ---------------- launch ----------------
extern "C" void kernel_launch(void* const* d_in, const int* in_sizes, int n_in,
                              void* d_out, int out_size)
{
    const float* feat = (const float*)d_in[0];
    const float* w1   = (const float*)d_in[1];
    const float* b1   = (const float*)d_in[2];
    const float* w2   = (const float*)d_in[3];
    const float* b2   = (const float*)d_in[4];
    float* out = (float*)d_out;

    cudaFuncSetAttribute(gemm1_fp16, cudaFuncAttributeMaxDynamicSharedMemorySize, G1_SMEM);
    cudaFuncSetAttribute(logits_f16, cudaFuncAttributeMaxDynamicSharedMemorySize, SK_SMEM);
    cudaFuncSetAttribute(sim_f16,    cudaFuncAttributeMaxDynamicSharedMemorySize, SK_SMEM);

    prep_kernel<<<PREP_BLOCKS, 256>>>(feat, w1, w2);
    gemm1_fp16<<<dim3(HDIM / 128, NROWS / 128), 256, G1_SMEM>>>(b1);
    logits_f16<<<NROWS / 128, 256, SK_SMEM>>>(b2);
    scatter_kernel<<<NROWS / 256, 256>>>();
    segsum_sorted<<<dim3(DDIM / 256, NROWS / SEG_CHUNK), 128>>>();
    centroid_f16<<<BPADR, 256>>>();
    sim_f16<<<NROWS / 128, 256, SK_SMEM>>>();
    finalize_kernel<<<1, 128>>>(out);
}

// round 13
// speedup vs baseline: 1.3711x; 1.0247x over previous
#include <cuda_runtime.h>
#include <cuda_fp16.h>
#include <math.h>
#include <stdint.h>

#define NROWS 16384
#define DDIM  2048
#define HDIM  512
#define CDIM  65
#define KPAIRS (DDIM / 2)
#define BPADR 96     // padded B rows for ldmatrix groups of 32

// ---------------- scratch (device globals; no allocation) ----------------
__device__ __half        g_h16[NROWS * HDIM];      // post-dropout hidden (fp16)
__device__ __half        g_feat16[NROWS * DDIM];   // feat converted to fp16
__device__ float         g_logits[NROWS * CDIM];
__device__ float         g_lse[NROWS];
__device__ int           g_pred[NROWS];
__device__ float         g_sump[CDIM];
__device__ float         g_ent;
__device__ float         g_ce;
__device__ float         g_csum[CDIM * DDIM];
__device__ int           g_cnt[CDIM];
__device__ int           g_fill[CDIM];             // scatter cursors (zeroed)
__device__ int           g_perm[NROWS];            // (class<<20) | row, sorted
__device__ unsigned      g_w1Th[HDIM * KPAIRS];    // half2 pairs, [n][k]
__device__ __half        g_w2T16[BPADR * HDIM];    // [n][k] fp16, rows>=CDIM zero
__device__ __half        g_cent16[BPADR * DDIM];   // [c][d] fp16 centroids

// ---------------- helpers ----------------
__device__ __forceinline__ unsigned pack_h2(float a, float b)
{
    __half2 h = __floats2half2_rn(a, b);
    return *reinterpret_cast<unsigned*>(&h);
}

__device__ __forceinline__ unsigned smem_u32(const void* p)
{
    unsigned a;
    asm("{ .reg .u64 t; cvta.to.shared.u64 t, %1; cvt.u32.u64 %0, t; }" : "=r"(a) : "l"(p));
    return a;
}

__device__ __forceinline__ void mma_f16(float c[4],
                                        unsigned a0, unsigned a1, unsigned a2, unsigned a3,
                                        unsigned b0, unsigned b1)
{
    asm volatile(
        "mma.sync.aligned.m16n8k16.row.col.f32.f16.f16.f32 "
        "{%0,%1,%2,%3}, {%4,%5,%6,%7}, {%8,%9}, {%0,%1,%2,%3};"
        : "+f"(c[0]), "+f"(c[1]), "+f"(c[2]), "+f"(c[3])
        : "r"(a0), "r"(a1), "r"(a2), "r"(a3), "r"(b0), "r"(b1));
}

__device__ __forceinline__ void ldsm_x4(unsigned& r0, unsigned& r1, unsigned& r2, unsigned& r3,
                                        unsigned saddr)
{
    asm volatile("ldmatrix.sync.aligned.m8n8.x4.shared.b16 {%0,%1,%2,%3}, [%4];"
                 : "=r"(r0), "=r"(r1), "=r"(r2), "=r"(r3) : "r"(saddr));
}

#define CP_ASYNC16(dst, src) \
    asm volatile("cp.async.cg.shared.global [%0], [%1], 16;" :: "r"(dst), "l"(src))
#define CP_COMMIT() asm volatile("cp.async.commit_group;")
#define CP_WAIT(n)  asm volatile("cp.async.wait_group %0;" :: "n"(n))

// ---------------- threefry2x32 (JAX partitionable, key = (0, 42)) ----------------
__device__ __forceinline__ void threefry2x32_42(unsigned c0, unsigned c1,
                                                unsigned& o0, unsigned& o1)
{
    const unsigned ks0 = 0u;
    const unsigned ks1 = 42u;
    const unsigned ks2 = 0x1BD11BDAu ^ 0u ^ 42u;
    unsigned x0 = c0 + ks0;
    unsigned x1 = c1 + ks1;
#define TF_ROUND(r) { x0 += x1; x1 = (x1 << (r)) | (x1 >> (32 - (r))); x1 ^= x0; }
    TF_ROUND(13) TF_ROUND(15) TF_ROUND(26) TF_ROUND(6)
    x0 += ks1; x1 += ks2 + 1u;
    TF_ROUND(17) TF_ROUND(29) TF_ROUND(16) TF_ROUND(24)
    x0 += ks2; x1 += ks0 + 2u;
    TF_ROUND(13) TF_ROUND(15) TF_ROUND(26) TF_ROUND(6)
    x0 += ks0; x1 += ks1 + 3u;
    TF_ROUND(17) TF_ROUND(29) TF_ROUND(16) TF_ROUND(24)
    x0 += ks1; x1 += ks2 + 4u;
    TF_ROUND(13) TF_ROUND(15) TF_ROUND(26) TF_ROUND(6)
    x0 += ks2; x1 += ks0 + 5u;
#undef TF_ROUND
    o0 = x0; o1 = x1;
}

__device__ __forceinline__ bool keep_bit(unsigned idx)
{
    unsigned a, b;
    threefry2x32_42(0u, idx, a, b);
    return (b >> 31) == 0u;
}

// ============================================================================
// prep: feat->fp16, w1 transpose->fp16, w2 transpose->fp16, zero accumulators
// ============================================================================
#define FEAT_BLOCKS (NROWS * DDIM / (256 * 8))          // 16384
#define W1T_BLOCKS  ((DDIM / 32) * (HDIM / 32))         // 1024
#define W2T_BLOCKS  ((BPADR * HDIM + 255) / 256)        // 192
#define ZERO_BLOCKS ((CDIM * DDIM + 255) / 256)         // 520
#define PREP_BLOCKS (FEAT_BLOCKS + W1T_BLOCKS + W2T_BLOCKS + ZERO_BLOCKS)

__global__ void __launch_bounds__(256) prep_kernel(const float* __restrict__ feat,
                                                   const float* __restrict__ w1,
                                                   const float* __restrict__ w2)
{
    __shared__ float t[32][33];
    const int b = blockIdx.x;
    const int tid = threadIdx.x;

    if (b < FEAT_BLOCKS) {
        size_t i = ((size_t)b * 256 + tid) * 8;
        float4 v0 = *reinterpret_cast<const float4*>(feat + i);
        float4 v1 = *reinterpret_cast<const float4*>(feat + i + 4);
        uint4 o;
        o.x = pack_h2(v0.x, v0.y);
        o.y = pack_h2(v0.z, v0.w);
        o.z = pack_h2(v1.x, v1.y);
        o.w = pack_h2(v1.z, v1.w);
        *reinterpret_cast<uint4*>(&g_feat16[i]) = o;
    } else if (b < FEAT_BLOCKS + W1T_BLOCKS) {
        int q = b - FEAT_BLOCKS;
        int k0 = (q & 63) * 32, n0 = (q >> 6) * 32;
        int x = tid & 31, y = tid >> 5;
#pragma unroll
        for (int i = y; i < 32; i += 8) t[i][x] = w1[(size_t)(k0 + i) * HDIM + n0 + x];
        __syncthreads();
#pragma unroll
        for (int i = y; i < 16; i += 8)
            g_w1Th[(size_t)(n0 + x) * KPAIRS + k0 / 2 + i] = pack_h2(t[2 * i][x], t[2 * i + 1][x]);
    } else if (b < FEAT_BLOCKS + W1T_BLOCKS + W2T_BLOCKS) {
        int i = (b - FEAT_BLOCKS - W1T_BLOCKS) * 256 + tid;
        if (i < BPADR * HDIM) {
            int n = i / HDIM, k = i - n * HDIM;
            g_w2T16[i] = (n < CDIM) ? __float2half_rn(w2[k * CDIM + n]) : __float2half_rn(0.f);
        }
    } else {
        int i = (b - FEAT_BLOCKS - W1T_BLOCKS - W2T_BLOCKS) * 256 + tid;
        if (i < CDIM * DDIM) g_csum[i] = 0.f;
        if (i < CDIM) { g_sump[i] = 0.f; g_cnt[i] = 0; g_fill[i] = 0; }
        if (i == 0) { g_ent = 0.f; g_ce = 0.f; }
    }
}

// ============================================================================
// GEMM1 (fp16, 2-stage cp.async + ldmatrix): g_h16 = dropout(relu(feat@w1+b1))
// ============================================================================
#define G1_SMEM (2 * 32768)

__global__ void __launch_bounds__(256) gemm1_fp16(const float* __restrict__ bias)
{
    extern __shared__ __align__(1024) char dsm[];
    __shared__ float sb[128];

    const unsigned sbase = smem_u32(dsm);
    const int tid  = threadIdx.x;
    const int lane = tid & 31;
    const int w    = tid >> 5;
    const int g    = lane >> 2;
    const int t    = lane & 3;
    const int wm   = w & 1;
    const int wn   = w >> 1;
    const int brow = blockIdx.y * 128;
    const int bcol = blockIdx.x * 128;

    if (tid < 128) sb[tid] = bias[bcol + tid];

    const int NT = DDIM / 64;           // 32
    const int cr = tid >> 3;
    const int cc = tid & 7;

    auto issue_copy = [&](int kt) {
        const unsigned aoff = (kt & 1) * 32768u;
        const unsigned boff = aoff + 16384u;
        const __half* Ag = &g_feat16[(size_t)brow * DDIM + kt * 64];
        const unsigned* Bg = &g_w1Th[(size_t)bcol * KPAIRS + kt * 32];
#pragma unroll
        for (int i = 0; i < 4; i++) {
            int r = cr + 32 * i;
            unsigned dsw = (unsigned)((cc ^ (r & 7)) << 4);
            CP_ASYNC16(sbase + aoff + r * 128 + dsw, Ag + (size_t)r * DDIM + cc * 8);
            CP_ASYNC16(sbase + boff + r * 128 + dsw, Bg + (size_t)r * KPAIRS + cc * 4);
        }
        CP_COMMIT();
    };

    float acc[4][4][4];
#pragma unroll
    for (int i = 0; i < 4; i++)
#pragma unroll
        for (int j = 0; j < 4; j++)
#pragma unroll
            for (int c = 0; c < 4; c++) acc[i][j][c] = 0.f;

    issue_copy(0);

    for (int kt = 0; kt < NT; kt++) {
        if (kt + 1 < NT) { issue_copy(kt + 1); CP_WAIT(1); }
        else             { CP_WAIT(0); }
        __syncthreads();

        const unsigned aoff = (kt & 1) * 32768u;
        const unsigned boff = aoff + 16384u;

        const int bn = wn * 32 + lane;
        const unsigned bline = sbase + boff + bn * 128;
        const int arl = (lane & 15);
        const int ach = (lane >> 4);

#pragma unroll
        for (int ks = 0; ks < 4; ks++) {
            unsigned b0[4], b1[4];
            {
                int c0 = (2 * ks) ^ (bn & 7);
                int c1 = (2 * ks + 1) ^ (bn & 7);
                ldsm_x4(b0[0], b0[1], b0[2], b0[3], bline + (c0 << 4));
                ldsm_x4(b1[0], b1[1], b1[2], b1[3], bline + (c1 << 4));
            }
#pragma unroll
            for (int mt = 0; mt < 4; mt++) {
                int row = wm * 64 + mt * 16 + arl;
                int ch  = (2 * ks + ach) ^ (row & 7);
                unsigned a0, a1, a2, a3;
                ldsm_x4(a0, a1, a2, a3, sbase + aoff + row * 128 + (ch << 4));
#pragma unroll
                for (int nt = 0; nt < 4; nt++)
                    mma_f16(acc[mt][nt], a0, a1, a2, a3, b0[nt], b1[nt]);
            }
        }
        __syncthreads();
    }

#pragma unroll
    for (int mt = 0; mt < 4; mt++) {
#pragma unroll
        for (int h = 0; h < 2; h++) {
            int row = brow + wm * 64 + mt * 16 + g + 8 * h;
#pragma unroll
            for (int nt = 0; nt < 4; nt++) {
                int colL = wn * 32 + nt * 8 + 2 * t;
                unsigned i0 = (unsigned)(row * HDIM + bcol + colL);
                float v0 = fmaxf(acc[mt][nt][2 * h + 0] + sb[colL], 0.f);
                float v1 = fmaxf(acc[mt][nt][2 * h + 1] + sb[colL + 1], 0.f);
                unsigned o = pack_h2(keep_bit(i0)     ? (v0 + v0) : 0.f,
                                     keep_bit(i0 + 1) ? (v1 + v1) : 0.f);
                *reinterpret_cast<unsigned*>(&g_h16[i0]) = o;
            }
        }
    }
}

// ============================================================================
// logits (fp16, 2-stage, 4 warps x 32 rows): fused stats/argmax/counts.
// ============================================================================
#define SK_SMEM 57344

__global__ void __launch_bounds__(128) logits_f16(const float* __restrict__ b2)
{
    extern __shared__ __align__(1024) char dsm[];
    const unsigned sbase = smem_u32(dsm);
    const int tid  = threadIdx.x;
    const int lane = tid & 31;
    const int w    = tid >> 5;          // 0..3
    const int g    = lane >> 2;
    const int t    = lane & 3;
    const int row0 = blockIdx.x * 128;
    const int cr   = tid >> 3;          // 0..15
    const int cc   = tid & 7;

    auto issue_copy = [&](int kt) {
        const unsigned aoff = (kt & 1) * 28672u;
        const unsigned boff = aoff + 16384u;
        const __half* Ag = &g_h16[(size_t)row0 * HDIM + kt * 64];
        const __half* Bg = &g_w2T16[kt * 64];
#pragma unroll
        for (int i = 0; i < 8; i++) {
            int r = cr + 16 * i;
            unsigned dsw = (unsigned)((cc ^ (r & 7)) << 4);
            CP_ASYNC16(sbase + aoff + r * 128 + dsw, Ag + (size_t)r * HDIM + cc * 8);
        }
#pragma unroll
        for (int i = 0; i < 6; i++) {
            int q = tid + 128 * i;
            int r = q >> 3, c = q & 7;
            unsigned dsw = (unsigned)((c ^ (r & 7)) << 4);
            CP_ASYNC16(sbase + boff + r * 128 + dsw, Bg + (size_t)r * HDIM + c * 8);
        }
        CP_COMMIT();
    };

    float acc[2][10][4];
#pragma unroll
    for (int m = 0; m < 2; m++)
#pragma unroll
        for (int n = 0; n < 10; n++)
#pragma unroll
            for (int c = 0; c < 4; c++) acc[m][n][c] = 0.f;

    issue_copy(0);
    const int NT = HDIM / 64;   // 8
    for (int kt = 0; kt < NT; kt++) {
        if (kt + 1 < NT) { issue_copy(kt + 1); CP_WAIT(1); }
        else             { CP_WAIT(0); }
        __syncthreads();

        const unsigned aoff = (kt & 1) * 28672u;
        const unsigned boff = aoff + 16384u;
        const int arl = lane & 15;
        const int ach = lane >> 4;

#pragma unroll
        for (int ks = 0; ks < 4; ks++) {
            unsigned b0[12], b1[12];
#pragma unroll
            for (int gr = 0; gr < 3; gr++) {
                int bn = gr * 32 + lane;
                unsigned bline = sbase + boff + bn * 128;
                int c0 = (2 * ks) ^ (bn & 7);
                int c1 = (2 * ks + 1) ^ (bn & 7);
                ldsm_x4(b0[gr*4+0], b0[gr*4+1], b0[gr*4+2], b0[gr*4+3], bline + (c0 << 4));
                ldsm_x4(b1[gr*4+0], b1[gr*4+1], b1[gr*4+2], b1[gr*4+3], bline + (c1 << 4));
            }
#pragma unroll
            for (int mt = 0; mt < 2; mt++) {
                int row = w * 32 + mt * 16 + arl;
                int ch  = (2 * ks + ach) ^ (row & 7);
                unsigned a0, a1, a2, a3;
                ldsm_x4(a0, a1, a2, a3, sbase + aoff + row * 128 + (ch << 4));
#pragma unroll
                for (int nt = 0; nt < 10; nt++)
                    mma_f16(acc[mt][nt], a0, a1, a2, a3, b0[nt], b1[nt]);
            }
        }
        __syncthreads();
    }

    float su[10][2];
#pragma unroll
    for (int n = 0; n < 10; n++) { su[n][0] = 0.f; su[n][1] = 0.f; }
    float entL = 0.f;

#pragma unroll
    for (int mt = 0; mt < 2; mt++)
#pragma unroll
    for (int half = 0; half < 2; half++) {
        int row = row0 + w * 32 + mt * 16 + g + 8 * half;
        int ci  = 2 * half;

        float v[10][2];
        float m = -1e30f;
#pragma unroll
        for (int nt = 0; nt < 10; nt++)
#pragma unroll
            for (int j = 0; j < 2; j++) {
                int col = nt * 8 + 2 * t + j;
                v[nt][j] = (col < CDIM) ? acc[mt][nt][ci + j] + b2[col] : -1e30f;
                m = fmaxf(m, v[nt][j]);
            }
        m = fmaxf(m, __shfl_xor_sync(0xffffffffu, m, 1));
        m = fmaxf(m, __shfl_xor_sync(0xffffffffu, m, 2));

        float s = 0.f;
#pragma unroll
        for (int nt = 0; nt < 10; nt++)
#pragma unroll
            for (int j = 0; j < 2; j++) {
                int col = nt * 8 + 2 * t + j;
                if (col < CDIM) s += expf(v[nt][j] - m);
            }
        s += __shfl_xor_sync(0xffffffffu, s, 1);
        s += __shfl_xor_sync(0xffffffffu, s, 2);
        float lse = m + logf(s);

        float bv = -1e30f; int bi = CDIM;
#pragma unroll
        for (int nt = 0; nt < 10; nt++)
#pragma unroll
            for (int j = 0; j < 2; j++) {
                int col = nt * 8 + 2 * t + j;
                if (col < CDIM) {
                    float p = expf(v[nt][j] - lse);
                    entL += p * logf(p + 1e-6f);
                    su[nt][j] += p;
                    g_logits[row * CDIM + col] = v[nt][j];
                    if (v[nt][j] > bv || (v[nt][j] == bv && col < bi)) { bv = v[nt][j]; bi = col; }
                }
            }
#pragma unroll
        for (int o = 1; o <= 2; o <<= 1) {
            float ov = __shfl_xor_sync(0xffffffffu, bv, o);
            int   oi = __shfl_xor_sync(0xffffffffu, bi, o);
            if (ov > bv || (ov == bv && oi < bi)) { bv = ov; bi = oi; }
        }
        if (t == 0) {
            g_lse[row]  = lse;
            g_pred[row] = bi;
            atomicAdd(&g_cnt[bi], 1);
        }
    }

#pragma unroll
    for (int o = 16; o > 0; o >>= 1) entL += __shfl_xor_sync(0xffffffffu, entL, o);
    if (lane == 0) atomicAdd(&g_ent, entL);

#pragma unroll
    for (int o = 4; o <= 16; o <<= 1)
#pragma unroll
        for (int nt = 0; nt < 10; nt++)
#pragma unroll
            for (int j = 0; j < 2; j++)
                su[nt][j] += __shfl_xor_sync(0xffffffffu, su[nt][j], o);
    if (g == 0) {
#pragma unroll
        for (int nt = 0; nt < 10; nt++)
#pragma unroll
            for (int j = 0; j < 2; j++) {
                int col = nt * 8 + 2 * t + j;
                if (col < CDIM) atomicAdd(&g_sump[col], su[nt][j]);
            }
    }
}

// ---- scatter: block-aggregated counting sort -> g_perm = (class<<20)|row ----
__global__ void __launch_bounds__(256) scatter_kernel()
{
    __shared__ int sstart[CDIM];
    __shared__ int hist[CDIM];
    __shared__ int basec[CDIM];
    const int tid = threadIdx.x;
    if (tid < CDIM) hist[tid] = 0;
    if (tid == 0) {
        int acc = 0;
        for (int c = 0; c < CDIM; c++) { sstart[c] = acc; acc += g_cnt[c]; }
    }
    __syncthreads();

    int i = blockIdx.x * 256 + tid;
    int c = g_pred[i];
    int loc = atomicAdd(&hist[c], 1);
    __syncthreads();
    if (tid < CDIM && hist[tid] > 0)
        basec[tid] = atomicAdd(&g_fill[tid], hist[tid]);
    __syncthreads();
    g_perm[sstart[c] + basec[c] + loc] = (c << 20) | i;
}

// ---- segsum over fixed 256-row chunks of sorted order ----
#define SEG_CHUNK 256
__global__ void __launch_bounds__(128) segsum_sorted()
{
    __shared__ int spk[SEG_CHUNK];

    const int t    = threadIdx.x;
    const int col2 = blockIdx.x * 128 + t;          // half2 column
    const int r0   = blockIdx.y * SEG_CHUNK;

    for (int i = t; i < SEG_CHUNK; i += 128)
        spk[i] = g_perm[r0 + i];
    __syncthreads();

    const unsigned* f2 = reinterpret_cast<const unsigned*>(g_feat16);
    float rx = 0.f, ry = 0.f;
    int cur = spk[0] >> 20;

    unsigned buf[8];
#pragma unroll
    for (int j = 0; j < 8; j++)
        buf[j] = f2[(size_t)(spk[j] & 0xFFFFF) * (DDIM / 2) + col2];

    for (int base = 0; base < SEG_CHUNK; base += 8) {
        unsigned nbuf[8];
        if (base + 8 < SEG_CHUNK) {
#pragma unroll
            for (int j = 0; j < 8; j++)
                nbuf[j] = f2[(size_t)(spk[base + 8 + j] & 0xFFFFF) * (DDIM / 2) + col2];
        }
#pragma unroll
        for (int j = 0; j < 8; j++) {
            int c = spk[base + j] >> 20;
            if (c != cur) {
                atomicAdd(&g_csum[cur * DDIM + 2 * col2],     rx);
                atomicAdd(&g_csum[cur * DDIM + 2 * col2 + 1], ry);
                rx = 0.f; ry = 0.f; cur = c;
            }
            float2 v = __half22float2(*reinterpret_cast<__half2*>(&buf[j]));
            rx += v.x; ry += v.y;
        }
#pragma unroll
        for (int j = 0; j < 8; j++) buf[j] = nbuf[j];
    }
    atomicAdd(&g_csum[cur * DDIM + 2 * col2],     rx);
    atomicAdd(&g_csum[cur * DDIM + 2 * col2 + 1], ry);
}

// ---- finalize centroids (normalized), K-major fp16; grid = 96 ----
__global__ void __launch_bounds__(256) centroid_f16()
{
    __shared__ float red[256];
    const int c = blockIdx.x;
    const int t = threadIdx.x;
    if (c >= CDIM) {
        for (int d = t; d < DDIM; d += 256) g_cent16[(size_t)c * DDIM + d] = __float2half_rn(0.f);
        return;
    }
    const int cnt = g_cnt[c];
    const float denom = fmaxf((float)cnt, 1.f);

    float ssq = 0.f;
    for (int d = t; d < DDIM; d += 256) {
        float mv = g_csum[c * DDIM + d] / denom;
        ssq += mv * mv;
    }
    red[t] = ssq;
    __syncthreads();
    for (int o = 128; o > 0; o >>= 1) { if (t < o) red[t] += red[t + o]; __syncthreads(); }
    float nrm   = sqrtf(red[0]);
    float scale = (cnt > 0) ? 1.f / (denom * fmaxf(nrm, 1e-12f)) : 0.f;

    for (int d = t; d < DDIM; d += 256)
        g_cent16[(size_t)c * DDIM + d] = __float2half_rn(g_csum[c * DDIM + d] * scale);
}

// ---- sim (fp16, 2-stage, 4 warps x 32 rows): fused argmax + CE ----
__global__ void __launch_bounds__(128) sim_f16()
{
    extern __shared__ __align__(1024) char dsm[];
    const unsigned sbase = smem_u32(dsm);
    const int tid  = threadIdx.x;
    const int lane = tid & 31;
    const int w    = tid >> 5;
    const int t    = lane & 3;
    const int row0 = blockIdx.x * 128;
    const int cr   = tid >> 3;
    const int cc   = tid & 7;

    auto issue_copy = [&](int kt) {
        const unsigned aoff = (kt & 1) * 28672u;
        const unsigned boff = aoff + 16384u;
        const __half* Ag = &g_feat16[(size_t)row0 * DDIM + kt * 64];
        const __half* Bg = &g_cent16[kt * 64];
#pragma unroll
        for (int i = 0; i < 8; i++) {
            int r = cr + 16 * i;
            unsigned dsw = (unsigned)((cc ^ (r & 7)) << 4);
            CP_ASYNC16(sbase + aoff + r * 128 + dsw, Ag + (size_t)r * DDIM + cc * 8);
        }
#pragma unroll
        for (int i = 0; i < 6; i++) {
            int q = tid + 128 * i;
            int r = q >> 3, c = q & 7;
            unsigned dsw = (unsigned)((c ^ (r & 7)) << 4);
            CP_ASYNC16(sbase + boff + r * 128 + dsw, Bg + (size_t)r * DDIM + c * 8);
        }
        CP_COMMIT();
    };

    float acc[2][10][4];
#pragma unroll
    for (int m = 0; m < 2; m++)
#pragma unroll
        for (int n = 0; n < 10; n++)
#pragma unroll
            for (int c = 0; c < 4; c++) acc[m][n][c] = 0.f;

    issue_copy(0);
    const int NT = DDIM / 64;   // 32
    for (int kt = 0; kt < NT; kt++) {
        if (kt + 1 < NT) { issue_copy(kt + 1); CP_WAIT(1); }
        else             { CP_WAIT(0); }
        __syncthreads();

        const unsigned aoff = (kt & 1) * 28672u;
        const unsigned boff = aoff + 16384u;
        const int arl = lane & 15;
        const int ach = lane >> 4;

#pragma unroll
        for (int ks = 0; ks < 4; ks++) {
            unsigned b0[12], b1[12];
#pragma unroll
            for (int gr = 0; gr < 3; gr++) {
                int bn = gr * 32 + lane;
                unsigned bline = sbase + boff + bn * 128;
                int c0 = (2 * ks) ^ (bn & 7);
                int c1 = (2 * ks + 1) ^ (bn & 7);
                ldsm_x4(b0[gr*4+0], b0[gr*4+1], b0[gr*4+2], b0[gr*4+3], bline + (c0 << 4));
                ldsm_x4(b1[gr*4+0], b1[gr*4+1], b1[gr*4+2], b1[gr*4+3], bline + (c1 << 4));
            }
#pragma unroll
            for (int mt = 0; mt < 2; mt++) {
                int row = w * 32 + mt * 16 + arl;
                int ch  = (2 * ks + ach) ^ (row & 7);
                unsigned a0, a1, a2, a3;
                ldsm_x4(a0, a1, a2, a3, sbase + aoff + row * 128 + (ch << 4));
#pragma unroll
                for (int nt = 0; nt < 10; nt++)
                    mma_f16(acc[mt][nt], a0, a1, a2, a3, b0[nt], b1[nt]);
            }
        }
        __syncthreads();
    }

    const int g = lane >> 2;
    float ceL = 0.f;
#pragma unroll
    for (int mt = 0; mt < 2; mt++)
#pragma unroll
    for (int half = 0; half < 2; half++) {
        int row = row0 + w * 32 + mt * 16 + g + 8 * half;
        int ci  = 2 * half;

        float bv = -1e30f; int bi = CDIM;
#pragma unroll
        for (int nt = 0; nt < 10; nt++)
#pragma unroll
            for (int j = 0; j < 2; j++) {
                int col = nt * 8 + 2 * t + j;
                if (col < CDIM) {
                    float vv = acc[mt][nt][ci + j];
                    if (vv > bv || (vv == bv && col < bi)) { bv = vv; bi = col; }
                }
            }
#pragma unroll
        for (int o = 1; o <= 2; o <<= 1) {
            float ov = __shfl_xor_sync(0xffffffffu, bv, o);
            int   oi = __shfl_xor_sync(0xffffffffu, bi, o);
            if (ov > bv || (ov == bv && oi < bi)) { bv = ov; bi = oi; }
        }
        if (t == 0)
            ceL += g_lse[row] - g_logits[row * CDIM + bi];
    }
#pragma unroll
    for (int o = 16; o > 0; o >>= 1) ceL += __shfl_xor_sync(0xffffffffu, ceL, o);
    if (lane == 0) atomicAdd(&g_ce, ceL);
}

// ---------------- final scalar ----------------
__global__ void finalize_kernel(float* __restrict__ out)
{
    __shared__ float red[128];
    int t = threadIdx.x;
    float v = 0.f;
    if (t < CDIM) {
        float mp = g_sump[t] * (1.f / NROWS);
        v = mp * logf(mp + 1e-6f);
    }
    red[t] = v;
    __syncthreads();
    for (int o = 64; o > 0; o >>= 1) { if (t < o) red[t] += red[t + o]; __syncthreads(); }
    if (t == 0) {
        float entropy = -g_ent * (1.f / NROWS);
        float ce      =  g_ce  * (1.f / NROWS);
        out[0] = entropy + red[0] + 0.3f * ce;
    }
}

// ---------------- launch ----------------
extern "C" void kernel_launch(void* const* d_in, const int* in_sizes, int n_in,
                              void* d_out, int out_size)
{
    const float* feat = (const float*)d_in[0];
    const float* w1   = (const float*)d_in[1];
    const float* b1   = (const float*)d_in[2];
    const float* w2   = (const float*)d_in[3];
    const float* b2   = (const float*)d_in[4];
    float* out = (float*)d_out;

    cudaFuncSetAttribute(gemm1_fp16, cudaFuncAttributeMaxDynamicSharedMemorySize, G1_SMEM);
    cudaFuncSetAttribute(logits_f16, cudaFuncAttributeMaxDynamicSharedMemorySize, SK_SMEM);
    cudaFuncSetAttribute(sim_f16,    cudaFuncAttributeMaxDynamicSharedMemorySize, SK_SMEM);

    prep_kernel<<<PREP_BLOCKS, 256>>>(feat, w1, w2);
    gemm1_fp16<<<dim3(HDIM / 128, NROWS / 128), 256, G1_SMEM>>>(b1);
    logits_f16<<<NROWS / 128, 128, SK_SMEM>>>(b2);
    scatter_kernel<<<NROWS / 256, 256>>>();
    segsum_sorted<<<dim3(DDIM / 256, NROWS / SEG_CHUNK), 128>>>();
    centroid_f16<<<BPADR, 256>>>();
    sim_f16<<<NROWS / 128, 128, SK_SMEM>>>();
    finalize_kernel<<<1, 128>>>(out);
}

// round 14
// speedup vs baseline: 1.3850x; 1.0101x over previous
#include <cuda_runtime.h>
#include <cuda_fp16.h>
#include <math.h>
#include <stdint.h>

#define NROWS 16384
#define DDIM  2048
#define HDIM  512
#define CDIM  65
#define KPAIRS (DDIM / 2)
#define BPADR 96     // padded B rows for ldmatrix groups of 32

// ---------------- scratch (device globals; no allocation) ----------------
__device__ __half        g_h16[NROWS * HDIM];      // post-dropout hidden (fp16)
__device__ __half        g_feat16[NROWS * DDIM];   // feat converted to fp16
__device__ float         g_logits[NROWS * CDIM];
__device__ float         g_lse[NROWS];
__device__ int           g_pred[NROWS];
__device__ float         g_sump[CDIM];
__device__ float         g_ent;
__device__ float         g_ce;
__device__ float         g_csum[CDIM * DDIM];
__device__ int           g_cnt[CDIM];
__device__ int           g_fill[CDIM];             // scatter cursors (zeroed)
__device__ int           g_perm[NROWS];            // (class<<20) | row, sorted
__device__ unsigned      g_w1Th[HDIM * KPAIRS];    // half2 pairs, [n][k]
__device__ __half        g_w2T16[BPADR * HDIM];    // [n][k] fp16, rows>=CDIM zero
__device__ __half        g_cent16[BPADR * DDIM];   // [c][d] fp16 centroids

// ---------------- helpers ----------------
__device__ __forceinline__ unsigned pack_h2(float a, float b)
{
    __half2 h = __floats2half2_rn(a, b);
    return *reinterpret_cast<unsigned*>(&h);
}

__device__ __forceinline__ unsigned smem_u32(const void* p)
{
    unsigned a;
    asm("{ .reg .u64 t; cvta.to.shared.u64 t, %1; cvt.u32.u64 %0, t; }" : "=r"(a) : "l"(p));
    return a;
}

__device__ __forceinline__ void mma_f16(float c[4],
                                        unsigned a0, unsigned a1, unsigned a2, unsigned a3,
                                        unsigned b0, unsigned b1)
{
    asm volatile(
        "mma.sync.aligned.m16n8k16.row.col.f32.f16.f16.f32 "
        "{%0,%1,%2,%3}, {%4,%5,%6,%7}, {%8,%9}, {%0,%1,%2,%3};"
        : "+f"(c[0]), "+f"(c[1]), "+f"(c[2]), "+f"(c[3])
        : "r"(a0), "r"(a1), "r"(a2), "r"(a3), "r"(b0), "r"(b1));
}

__device__ __forceinline__ void ldsm_x4(unsigned& r0, unsigned& r1, unsigned& r2, unsigned& r3,
                                        unsigned saddr)
{
    asm volatile("ldmatrix.sync.aligned.m8n8.x4.shared.b16 {%0,%1,%2,%3}, [%4];"
                 : "=r"(r0), "=r"(r1), "=r"(r2), "=r"(r3) : "r"(saddr));
}

#define CP_ASYNC16(dst, src) \
    asm volatile("cp.async.cg.shared.global [%0], [%1], 16;" :: "r"(dst), "l"(src))
#define CP_COMMIT() asm volatile("cp.async.commit_group;")
#define CP_WAIT(n)  asm volatile("cp.async.wait_group %0;" :: "n"(n))

// ---------------- threefry2x32 (JAX partitionable, key = (0, 42)) ----------------
__device__ __forceinline__ void threefry2x32_42(unsigned c0, unsigned c1,
                                                unsigned& o0, unsigned& o1)
{
    const unsigned ks0 = 0u;
    const unsigned ks1 = 42u;
    const unsigned ks2 = 0x1BD11BDAu ^ 0u ^ 42u;
    unsigned x0 = c0 + ks0;
    unsigned x1 = c1 + ks1;
#define TF_ROUND(r) { x0 += x1; x1 = (x1 << (r)) | (x1 >> (32 - (r))); x1 ^= x0; }
    TF_ROUND(13) TF_ROUND(15) TF_ROUND(26) TF_ROUND(6)
    x0 += ks1; x1 += ks2 + 1u;
    TF_ROUND(17) TF_ROUND(29) TF_ROUND(16) TF_ROUND(24)
    x0 += ks2; x1 += ks0 + 2u;
    TF_ROUND(13) TF_ROUND(15) TF_ROUND(26) TF_ROUND(6)
    x0 += ks0; x1 += ks1 + 3u;
    TF_ROUND(17) TF_ROUND(29) TF_ROUND(16) TF_ROUND(24)
    x0 += ks1; x1 += ks2 + 4u;
    TF_ROUND(13) TF_ROUND(15) TF_ROUND(26) TF_ROUND(6)
    x0 += ks2; x1 += ks0 + 5u;
#undef TF_ROUND
    o0 = x0; o1 = x1;
}

__device__ __forceinline__ bool keep_bit(unsigned idx)
{
    unsigned a, b;
    threefry2x32_42(0u, idx, a, b);
    return (b >> 31) == 0u;
}

// ============================================================================
// prep: feat->fp16, w1 transpose->fp16, w2 transpose->fp16, zero accumulators
// ============================================================================
#define FEAT_BLOCKS (NROWS * DDIM / (256 * 8))          // 16384
#define W1T_BLOCKS  ((DDIM / 32) * (HDIM / 32))         // 1024
#define W2T_BLOCKS  ((BPADR * HDIM + 255) / 256)        // 192
#define ZERO_BLOCKS ((CDIM * DDIM + 255) / 256)         // 520
#define PREP_BLOCKS (FEAT_BLOCKS + W1T_BLOCKS + W2T_BLOCKS + ZERO_BLOCKS)

__global__ void __launch_bounds__(256) prep_kernel(const float* __restrict__ feat,
                                                   const float* __restrict__ w1,
                                                   const float* __restrict__ w2)
{
    __shared__ float t[32][33];
    const int b = blockIdx.x;
    const int tid = threadIdx.x;

    if (b < FEAT_BLOCKS) {
        size_t i = ((size_t)b * 256 + tid) * 8;
        float4 v0 = *reinterpret_cast<const float4*>(feat + i);
        float4 v1 = *reinterpret_cast<const float4*>(feat + i + 4);
        uint4 o;
        o.x = pack_h2(v0.x, v0.y);
        o.y = pack_h2(v0.z, v0.w);
        o.z = pack_h2(v1.x, v1.y);
        o.w = pack_h2(v1.z, v1.w);
        *reinterpret_cast<uint4*>(&g_feat16[i]) = o;
    } else if (b < FEAT_BLOCKS + W1T_BLOCKS) {
        int q = b - FEAT_BLOCKS;
        int k0 = (q & 63) * 32, n0 = (q >> 6) * 32;
        int x = tid & 31, y = tid >> 5;
#pragma unroll
        for (int i = y; i < 32; i += 8) t[i][x] = w1[(size_t)(k0 + i) * HDIM + n0 + x];
        __syncthreads();
#pragma unroll
        for (int i = y; i < 16; i += 8)
            g_w1Th[(size_t)(n0 + x) * KPAIRS + k0 / 2 + i] = pack_h2(t[2 * i][x], t[2 * i + 1][x]);
    } else if (b < FEAT_BLOCKS + W1T_BLOCKS + W2T_BLOCKS) {
        int i = (b - FEAT_BLOCKS - W1T_BLOCKS) * 256 + tid;
        if (i < BPADR * HDIM) {
            int n = i / HDIM, k = i - n * HDIM;
            g_w2T16[i] = (n < CDIM) ? __float2half_rn(w2[k * CDIM + n]) : __float2half_rn(0.f);
        }
    } else {
        int i = (b - FEAT_BLOCKS - W1T_BLOCKS - W2T_BLOCKS) * 256 + tid;
        if (i < CDIM * DDIM) g_csum[i] = 0.f;
        if (i < CDIM) { g_sump[i] = 0.f; g_cnt[i] = 0; g_fill[i] = 0; }
        if (i == 0) { g_ent = 0.f; g_ce = 0.f; }
    }
}

// ============================================================================
// GEMM1 (fp16, 2-stage cp.async + ldmatrix): g_h16 = dropout(relu(feat@w1+b1))
// CTA 128x128, BK=64, 256 threads, 8 warps of 32x64 (4 row-groups x 2 col-groups).
// ============================================================================
#define G1_SMEM (2 * 32768)

__global__ void __launch_bounds__(256) gemm1_fp16(const float* __restrict__ bias)
{
    extern __shared__ __align__(1024) char dsm[];
    __shared__ float sb[128];

    const unsigned sbase = smem_u32(dsm);
    const int tid  = threadIdx.x;
    const int lane = tid & 31;
    const int w    = tid >> 5;
    const int g    = lane >> 2;
    const int t    = lane & 3;
    const int wm   = w & 3;             // 4 row groups of 32
    const int wn   = w >> 2;            // 2 col groups of 64
    const int brow = blockIdx.y * 128;
    const int bcol = blockIdx.x * 128;

    if (tid < 128) sb[tid] = bias[bcol + tid];

    const int NT = DDIM / 64;           // 32
    const int cr = tid >> 3;
    const int cc = tid & 7;

    auto issue_copy = [&](int kt) {
        const unsigned aoff = (kt & 1) * 32768u;
        const unsigned boff = aoff + 16384u;
        const __half* Ag = &g_feat16[(size_t)brow * DDIM + kt * 64];
        const unsigned* Bg = &g_w1Th[(size_t)bcol * KPAIRS + kt * 32];
#pragma unroll
        for (int i = 0; i < 4; i++) {
            int r = cr + 32 * i;
            unsigned dsw = (unsigned)((cc ^ (r & 7)) << 4);
            CP_ASYNC16(sbase + aoff + r * 128 + dsw, Ag + (size_t)r * DDIM + cc * 8);
            CP_ASYNC16(sbase + boff + r * 128 + dsw, Bg + (size_t)r * KPAIRS + cc * 4);
        }
        CP_COMMIT();
    };

    float acc[2][8][4];
#pragma unroll
    for (int i = 0; i < 2; i++)
#pragma unroll
        for (int j = 0; j < 8; j++)
#pragma unroll
            for (int c = 0; c < 4; c++) acc[i][j][c] = 0.f;

    issue_copy(0);

    for (int kt = 0; kt < NT; kt++) {
        if (kt + 1 < NT) { issue_copy(kt + 1); CP_WAIT(1); }
        else             { CP_WAIT(0); }
        __syncthreads();

        const unsigned aoff = (kt & 1) * 32768u;
        const unsigned boff = aoff + 16384u;

        const int arl = (lane & 15);
        const int ach = (lane >> 4);

#pragma unroll
        for (int ks = 0; ks < 4; ks++) {
            unsigned b0[8], b1[8];
#pragma unroll
            for (int gr = 0; gr < 2; gr++) {
                int bn = wn * 64 + gr * 32 + lane;
                unsigned bline = sbase + boff + bn * 128;
                int c0 = (2 * ks) ^ (bn & 7);
                int c1 = (2 * ks + 1) ^ (bn & 7);
                ldsm_x4(b0[gr*4+0], b0[gr*4+1], b0[gr*4+2], b0[gr*4+3], bline + (c0 << 4));
                ldsm_x4(b1[gr*4+0], b1[gr*4+1], b1[gr*4+2], b1[gr*4+3], bline + (c1 << 4));
            }
#pragma unroll
            for (int mt = 0; mt < 2; mt++) {
                int row = wm * 32 + mt * 16 + arl;
                int ch  = (2 * ks + ach) ^ (row & 7);
                unsigned a0, a1, a2, a3;
                ldsm_x4(a0, a1, a2, a3, sbase + aoff + row * 128 + (ch << 4));
#pragma unroll
                for (int nt = 0; nt < 8; nt++)
                    mma_f16(acc[mt][nt], a0, a1, a2, a3, b0[nt], b1[nt]);
            }
        }
        __syncthreads();
    }

#pragma unroll
    for (int mt = 0; mt < 2; mt++) {
#pragma unroll
        for (int h = 0; h < 2; h++) {
            int row = brow + wm * 32 + mt * 16 + g + 8 * h;
#pragma unroll
            for (int nt = 0; nt < 8; nt++) {
                int colL = wn * 64 + nt * 8 + 2 * t;
                unsigned i0 = (unsigned)(row * HDIM + bcol + colL);
                float v0 = fmaxf(acc[mt][nt][2 * h + 0] + sb[colL], 0.f);
                float v1 = fmaxf(acc[mt][nt][2 * h + 1] + sb[colL + 1], 0.f);
                unsigned o = pack_h2(keep_bit(i0)     ? (v0 + v0) : 0.f,
                                     keep_bit(i0 + 1) ? (v1 + v1) : 0.f);
                *reinterpret_cast<unsigned*>(&g_h16[i0]) = o;
            }
        }
    }
}

// ============================================================================
// logits (fp16, 2-stage, 4 warps x 32 rows): fused stats/argmax/counts.
// ============================================================================
#define SK_SMEM 57344

__global__ void __launch_bounds__(128) logits_f16(const float* __restrict__ b2)
{
    extern __shared__ __align__(1024) char dsm[];
    const unsigned sbase = smem_u32(dsm);
    const int tid  = threadIdx.x;
    const int lane = tid & 31;
    const int w    = tid >> 5;          // 0..3
    const int g    = lane >> 2;
    const int t    = lane & 3;
    const int row0 = blockIdx.x * 128;
    const int cr   = tid >> 3;          // 0..15
    const int cc   = tid & 7;

    auto issue_copy = [&](int kt) {
        const unsigned aoff = (kt & 1) * 28672u;
        const unsigned boff = aoff + 16384u;
        const __half* Ag = &g_h16[(size_t)row0 * HDIM + kt * 64];
        const __half* Bg = &g_w2T16[kt * 64];
#pragma unroll
        for (int i = 0; i < 8; i++) {
            int r = cr + 16 * i;
            unsigned dsw = (unsigned)((cc ^ (r & 7)) << 4);
            CP_ASYNC16(sbase + aoff + r * 128 + dsw, Ag + (size_t)r * HDIM + cc * 8);
        }
#pragma unroll
        for (int i = 0; i < 6; i++) {
            int q = tid + 128 * i;
            int r = q >> 3, c = q & 7;
            unsigned dsw = (unsigned)((c ^ (r & 7)) << 4);
            CP_ASYNC16(sbase + boff + r * 128 + dsw, Bg + (size_t)r * HDIM + c * 8);
        }
        CP_COMMIT();
    };

    float acc[2][10][4];
#pragma unroll
    for (int m = 0; m < 2; m++)
#pragma unroll
        for (int n = 0; n < 10; n++)
#pragma unroll
            for (int c = 0; c < 4; c++) acc[m][n][c] = 0.f;

    issue_copy(0);
    const int NT = HDIM / 64;   // 8
    for (int kt = 0; kt < NT; kt++) {
        if (kt + 1 < NT) { issue_copy(kt + 1); CP_WAIT(1); }
        else             { CP_WAIT(0); }
        __syncthreads();

        const unsigned aoff = (kt & 1) * 28672u;
        const unsigned boff = aoff + 16384u;
        const int arl = lane & 15;
        const int ach = lane >> 4;

#pragma unroll
        for (int ks = 0; ks < 4; ks++) {
            unsigned b0[12], b1[12];
#pragma unroll
            for (int gr = 0; gr < 3; gr++) {
                int bn = gr * 32 + lane;
                unsigned bline = sbase + boff + bn * 128;
                int c0 = (2 * ks) ^ (bn & 7);
                int c1 = (2 * ks + 1) ^ (bn & 7);
                ldsm_x4(b0[gr*4+0], b0[gr*4+1], b0[gr*4+2], b0[gr*4+3], bline + (c0 << 4));
                ldsm_x4(b1[gr*4+0], b1[gr*4+1], b1[gr*4+2], b1[gr*4+3], bline + (c1 << 4));
            }
#pragma unroll
            for (int mt = 0; mt < 2; mt++) {
                int row = w * 32 + mt * 16 + arl;
                int ch  = (2 * ks + ach) ^ (row & 7);
                unsigned a0, a1, a2, a3;
                ldsm_x4(a0, a1, a2, a3, sbase + aoff + row * 128 + (ch << 4));
#pragma unroll
                for (int nt = 0; nt < 10; nt++)
                    mma_f16(acc[mt][nt], a0, a1, a2, a3, b0[nt], b1[nt]);
            }
        }
        __syncthreads();
    }

    float su[10][2];
#pragma unroll
    for (int n = 0; n < 10; n++) { su[n][0] = 0.f; su[n][1] = 0.f; }
    float entL = 0.f;

#pragma unroll
    for (int mt = 0; mt < 2; mt++)
#pragma unroll
    for (int half = 0; half < 2; half++) {
        int row = row0 + w * 32 + mt * 16 + g + 8 * half;
        int ci  = 2 * half;

        float v[10][2];
        float m = -1e30f;
#pragma unroll
        for (int nt = 0; nt < 10; nt++)
#pragma unroll
            for (int j = 0; j < 2; j++) {
                int col = nt * 8 + 2 * t + j;
                v[nt][j] = (col < CDIM) ? acc[mt][nt][ci + j] + b2[col] : -1e30f;
                m = fmaxf(m, v[nt][j]);
            }
        m = fmaxf(m, __shfl_xor_sync(0xffffffffu, m, 1));
        m = fmaxf(m, __shfl_xor_sync(0xffffffffu, m, 2));

        float s = 0.f;
#pragma unroll
        for (int nt = 0; nt < 10; nt++)
#pragma unroll
            for (int j = 0; j < 2; j++) {
                int col = nt * 8 + 2 * t + j;
                if (col < CDIM) s += expf(v[nt][j] - m);
            }
        s += __shfl_xor_sync(0xffffffffu, s, 1);
        s += __shfl_xor_sync(0xffffffffu, s, 2);
        float lse = m + logf(s);

        float bv = -1e30f; int bi = CDIM;
#pragma unroll
        for (int nt = 0; nt < 10; nt++)
#pragma unroll
            for (int j = 0; j < 2; j++) {
                int col = nt * 8 + 2 * t + j;
                if (col < CDIM) {
                    float p = expf(v[nt][j] - lse);
                    entL += p * logf(p + 1e-6f);
                    su[nt][j] += p;
                    g_logits[row * CDIM + col] = v[nt][j];
                    if (v[nt][j] > bv || (v[nt][j] == bv && col < bi)) { bv = v[nt][j]; bi = col; }
                }
            }
#pragma unroll
        for (int o = 1; o <= 2; o <<= 1) {
            float ov = __shfl_xor_sync(0xffffffffu, bv, o);
            int   oi = __shfl_xor_sync(0xffffffffu, bi, o);
            if (ov > bv || (ov == bv && oi < bi)) { bv = ov; bi = oi; }
        }
        if (t == 0) {
            g_lse[row]  = lse;
            g_pred[row] = bi;
            atomicAdd(&g_cnt[bi], 1);
        }
    }

#pragma unroll
    for (int o = 16; o > 0; o >>= 1) entL += __shfl_xor_sync(0xffffffffu, entL, o);
    if (lane == 0) atomicAdd(&g_ent, entL);

#pragma unroll
    for (int o = 4; o <= 16; o <<= 1)
#pragma unroll
        for (int nt = 0; nt < 10; nt++)
#pragma unroll
            for (int j = 0; j < 2; j++)
                su[nt][j] += __shfl_xor_sync(0xffffffffu, su[nt][j], o);
    if (g == 0) {
#pragma unroll
        for (int nt = 0; nt < 10; nt++)
#pragma unroll
            for (int j = 0; j < 2; j++) {
                int col = nt * 8 + 2 * t + j;
                if (col < CDIM) atomicAdd(&g_sump[col], su[nt][j]);
            }
    }
}

// ---- scatter: block-aggregated counting sort -> g_perm = (class<<20)|row ----
__global__ void __launch_bounds__(256) scatter_kernel()
{
    __shared__ int sstart[CDIM];
    __shared__ int hist[CDIM];
    __shared__ int basec[CDIM];
    const int tid = threadIdx.x;
    if (tid < CDIM) hist[tid] = 0;
    if (tid == 0) {
        int acc = 0;
        for (int c = 0; c < CDIM; c++) { sstart[c] = acc; acc += g_cnt[c]; }
    }
    __syncthreads();

    int i = blockIdx.x * 256 + tid;
    int c = g_pred[i];
    int loc = atomicAdd(&hist[c], 1);
    __syncthreads();
    if (tid < CDIM && hist[tid] > 0)
        basec[tid] = atomicAdd(&g_fill[tid], hist[tid]);
    __syncthreads();
    g_perm[sstart[c] + basec[c] + loc] = (c << 20) | i;
}

// ---- segsum over fixed 256-row chunks of sorted order ----
#define SEG_CHUNK 256
__global__ void __launch_bounds__(128) segsum_sorted()
{
    __shared__ int spk[SEG_CHUNK];

    const int t    = threadIdx.x;
    const int col2 = blockIdx.x * 128 + t;          // half2 column
    const int r0   = blockIdx.y * SEG_CHUNK;

    for (int i = t; i < SEG_CHUNK; i += 128)
        spk[i] = g_perm[r0 + i];
    __syncthreads();

    const unsigned* f2 = reinterpret_cast<const unsigned*>(g_feat16);
    float rx = 0.f, ry = 0.f;
    int cur = spk[0] >> 20;

    unsigned buf[8];
#pragma unroll
    for (int j = 0; j < 8; j++)
        buf[j] = f2[(size_t)(spk[j] & 0xFFFFF) * (DDIM / 2) + col2];

    for (int base = 0; base < SEG_CHUNK; base += 8) {
        unsigned nbuf[8];
        if (base + 8 < SEG_CHUNK) {
#pragma unroll
            for (int j = 0; j < 8; j++)
                nbuf[j] = f2[(size_t)(spk[base + 8 + j] & 0xFFFFF) * (DDIM / 2) + col2];
        }
#pragma unroll
        for (int j = 0; j < 8; j++) {
            int c = spk[base + j] >> 20;
            if (c != cur) {
                atomicAdd(&g_csum[cur * DDIM + 2 * col2],     rx);
                atomicAdd(&g_csum[cur * DDIM + 2 * col2 + 1], ry);
                rx = 0.f; ry = 0.f; cur = c;
            }
            float2 v = __half22float2(*reinterpret_cast<__half2*>(&buf[j]));
            rx += v.x; ry += v.y;
        }
#pragma unroll
        for (int j = 0; j < 8; j++) buf[j] = nbuf[j];
    }
    atomicAdd(&g_csum[cur * DDIM + 2 * col2],     rx);
    atomicAdd(&g_csum[cur * DDIM + 2 * col2 + 1], ry);
}

// ---- finalize centroids (normalized), K-major fp16; grid = 96 ----
__global__ void __launch_bounds__(256) centroid_f16()
{
    __shared__ float red[256];
    const int c = blockIdx.x;
    const int t = threadIdx.x;
    if (c >= CDIM) {
        for (int d = t; d < DDIM; d += 256) g_cent16[(size_t)c * DDIM + d] = __float2half_rn(0.f);
        return;
    }
    const int cnt = g_cnt[c];
    const float denom = fmaxf((float)cnt, 1.f);

    float ssq = 0.f;
    for (int d = t; d < DDIM; d += 256) {
        float mv = g_csum[c * DDIM + d] / denom;
        ssq += mv * mv;
    }
    red[t] = ssq;
    __syncthreads();
    for (int o = 128; o > 0; o >>= 1) { if (t < o) red[t] += red[t + o]; __syncthreads(); }
    float nrm   = sqrtf(red[0]);
    float scale = (cnt > 0) ? 1.f / (denom * fmaxf(nrm, 1e-12f)) : 0.f;

    for (int d = t; d < DDIM; d += 256)
        g_cent16[(size_t)c * DDIM + d] = __float2half_rn(g_csum[c * DDIM + d] * scale);
}

// ---- sim (fp16, 2-stage, 4 warps x 32 rows): fused argmax + CE ----
__global__ void __launch_bounds__(128) sim_f16()
{
    extern __shared__ __align__(1024) char dsm[];
    const unsigned sbase = smem_u32(dsm);
    const int tid  = threadIdx.x;
    const int lane = tid & 31;
    const int w    = tid >> 5;
    const int t    = lane & 3;
    const int row0 = blockIdx.x * 128;
    const int cr   = tid >> 3;
    const int cc   = tid & 7;

    auto issue_copy = [&](int kt) {
        const unsigned aoff = (kt & 1) * 28672u;
        const unsigned boff = aoff + 16384u;
        const __half* Ag = &g_feat16[(size_t)row0 * DDIM + kt * 64];
        const __half* Bg = &g_cent16[kt * 64];
#pragma unroll
        for (int i = 0; i < 8; i++) {
            int r = cr + 16 * i;
            unsigned dsw = (unsigned)((cc ^ (r & 7)) << 4);
            CP_ASYNC16(sbase + aoff + r * 128 + dsw, Ag + (size_t)r * DDIM + cc * 8);
        }
#pragma unroll
        for (int i = 0; i < 6; i++) {
            int q = tid + 128 * i;
            int r = q >> 3, c = q & 7;
            unsigned dsw = (unsigned)((c ^ (r & 7)) << 4);
            CP_ASYNC16(sbase + boff + r * 128 + dsw, Bg + (size_t)r * DDIM + c * 8);
        }
        CP_COMMIT();
    };

    float acc[2][10][4];
#pragma unroll
    for (int m = 0; m < 2; m++)
#pragma unroll
        for (int n = 0; n < 10; n++)
#pragma unroll
            for (int c = 0; c < 4; c++) acc[m][n][c] = 0.f;

    issue_copy(0);
    const int NT = DDIM / 64;   // 32
    for (int kt = 0; kt < NT; kt++) {
        if (kt + 1 < NT) { issue_copy(kt + 1); CP_WAIT(1); }
        else             { CP_WAIT(0); }
        __syncthreads();

        const unsigned aoff = (kt & 1) * 28672u;
        const unsigned boff = aoff + 16384u;
        const int arl = lane & 15;
        const int ach = lane >> 4;

#pragma unroll
        for (int ks = 0; ks < 4; ks++) {
            unsigned b0[12], b1[12];
#pragma unroll
            for (int gr = 0; gr < 3; gr++) {
                int bn = gr * 32 + lane;
                unsigned bline = sbase + boff + bn * 128;
                int c0 = (2 * ks) ^ (bn & 7);
                int c1 = (2 * ks + 1) ^ (bn & 7);
                ldsm_x4(b0[gr*4+0], b0[gr*4+1], b0[gr*4+2], b0[gr*4+3], bline + (c0 << 4));
                ldsm_x4(b1[gr*4+0], b1[gr*4+1], b1[gr*4+2], b1[gr*4+3], bline + (c1 << 4));
            }
#pragma unroll
            for (int mt = 0; mt < 2; mt++) {
                int row = w * 32 + mt * 16 + arl;
                int ch  = (2 * ks + ach) ^ (row & 7);
                unsigned a0, a1, a2, a3;
                ldsm_x4(a0, a1, a2, a3, sbase + aoff + row * 128 + (ch << 4));
#pragma unroll
                for (int nt = 0; nt < 10; nt++)
                    mma_f16(acc[mt][nt], a0, a1, a2, a3, b0[nt], b1[nt]);
            }
        }
        __syncthreads();
    }

    const int g = lane >> 2;
    float ceL = 0.f;
#pragma unroll
    for (int mt = 0; mt < 2; mt++)
#pragma unroll
    for (int half = 0; half < 2; half++) {
        int row = row0 + w * 32 + mt * 16 + g + 8 * half;
        int ci  = 2 * half;

        float bv = -1e30f; int bi = CDIM;
#pragma unroll
        for (int nt = 0; nt < 10; nt++)
#pragma unroll
            for (int j = 0; j < 2; j++) {
                int col = nt * 8 + 2 * t + j;
                if (col < CDIM) {
                    float vv = acc[mt][nt][ci + j];
                    if (vv > bv || (vv == bv && col < bi)) { bv = vv; bi = col; }
                }
            }
#pragma unroll
        for (int o = 1; o <= 2; o <<= 1) {
            float ov = __shfl_xor_sync(0xffffffffu, bv, o);
            int   oi = __shfl_xor_sync(0xffffffffu, bi, o);
            if (ov > bv || (ov == bv && oi < bi)) { bv = ov; bi = oi; }
        }
        if (t == 0)
            ceL += g_lse[row] - g_logits[row * CDIM + bi];
    }
#pragma unroll
    for (int o = 16; o > 0; o >>= 1) ceL += __shfl_xor_sync(0xffffffffu, ceL, o);
    if (lane == 0) atomicAdd(&g_ce, ceL);
}

// ---------------- final scalar ----------------
__global__ void finalize_kernel(float* __restrict__ out)
{
    __shared__ float red[128];
    int t = threadIdx.x;
    float v = 0.f;
    if (t < CDIM) {
        float mp = g_sump[t] * (1.f / NROWS);
        v = mp * logf(mp + 1e-6f);
    }
    red[t] = v;
    __syncthreads();
    for (int o = 64; o > 0; o >>= 1) { if (t < o) red[t] += red[t + o]; __syncthreads(); }
    if (t == 0) {
        float entropy = -g_ent * (1.f / NROWS);
        float ce      =  g_ce  * (1.f / NROWS);
        out[0] = entropy + red[0] + 0.3f * ce;
    }
}

// ---------------- launch ----------------
extern "C" void kernel_launch(void* const* d_in, const int* in_sizes, int n_in,
                              void* d_out, int out_size)
{
    const float* feat = (const float*)d_in[0];
    const float* w1   = (const float*)d_in[1];
    const float* b1   = (const float*)d_in[2];
    const float* w2   = (const float*)d_in[3];
    const float* b2   = (const float*)d_in[4];
    float* out = (float*)d_out;

    cudaFuncSetAttribute(gemm1_fp16, cudaFuncAttributeMaxDynamicSharedMemorySize, G1_SMEM);
    cudaFuncSetAttribute(logits_f16, cudaFuncAttributeMaxDynamicSharedMemorySize, SK_SMEM);
    cudaFuncSetAttribute(sim_f16,    cudaFuncAttributeMaxDynamicSharedMemorySize, SK_SMEM);

    prep_kernel<<<PREP_BLOCKS, 256>>>(feat, w1, w2);
    gemm1_fp16<<<dim3(HDIM / 128, NROWS / 128), 256, G1_SMEM>>>(b1);
    logits_f16<<<NROWS / 128, 128, SK_SMEM>>>(b2);
    scatter_kernel<<<NROWS / 256, 256>>>();
    segsum_sorted<<<dim3(DDIM / 256, NROWS / SEG_CHUNK), 128>>>();
    centroid_f16<<<BPADR, 256>>>();
    sim_f16<<<NROWS / 128, 128, SK_SMEM>>>();
    finalize_kernel<<<1, 128>>>(out);
}

// round 15
// speedup vs baseline: 1.4059x; 1.0150x over previous
#include <cuda_runtime.h>
#include <cuda_fp16.h>
#include <math.h>
#include <stdint.h>

#define NROWS 16384
#define DDIM  2048
#define HDIM  512
#define CDIM  65
#define KPAIRS (DDIM / 2)
#define BPADR 96     // padded B rows for ldmatrix groups of 32

// ---------------- scratch (device globals; no allocation) ----------------
__device__ __half        g_h16[NROWS * HDIM];      // post-dropout hidden (fp16)
__device__ __half        g_feat16[NROWS * DDIM];   // feat converted to fp16
__device__ float         g_logits[NROWS * CDIM];
__device__ float         g_lse[NROWS];
__device__ int           g_pred[NROWS];
__device__ float         g_sump[CDIM];
__device__ float         g_ent;
__device__ float         g_ce;
__device__ float         g_csum[CDIM * DDIM];
__device__ int           g_cnt[CDIM];
__device__ int           g_fill[CDIM];             // scatter cursors (zeroed)
__device__ int           g_perm[NROWS];            // (class<<20) | row, sorted
__device__ unsigned      g_w1Th[HDIM * KPAIRS];    // half2 pairs, [n][k]
__device__ __half        g_w2T16[BPADR * HDIM];    // [n][k] fp16, rows>=CDIM zero
__device__ __half        g_cent16[BPADR * DDIM];   // [c][d] fp16 centroids

// ---------------- helpers ----------------
__device__ __forceinline__ unsigned pack_h2(float a, float b)
{
    __half2 h = __floats2half2_rn(a, b);
    return *reinterpret_cast<unsigned*>(&h);
}

__device__ __forceinline__ unsigned smem_u32(const void* p)
{
    unsigned a;
    asm("{ .reg .u64 t; cvta.to.shared.u64 t, %1; cvt.u32.u64 %0, t; }" : "=r"(a) : "l"(p));
    return a;
}

__device__ __forceinline__ void mma_f16(float c[4],
                                        unsigned a0, unsigned a1, unsigned a2, unsigned a3,
                                        unsigned b0, unsigned b1)
{
    asm volatile(
        "mma.sync.aligned.m16n8k16.row.col.f32.f16.f16.f32 "
        "{%0,%1,%2,%3}, {%4,%5,%6,%7}, {%8,%9}, {%0,%1,%2,%3};"
        : "+f"(c[0]), "+f"(c[1]), "+f"(c[2]), "+f"(c[3])
        : "r"(a0), "r"(a1), "r"(a2), "r"(a3), "r"(b0), "r"(b1));
}

__device__ __forceinline__ void ldsm_x4(unsigned& r0, unsigned& r1, unsigned& r2, unsigned& r3,
                                        unsigned saddr)
{
    asm volatile("ldmatrix.sync.aligned.m8n8.x4.shared.b16 {%0,%1,%2,%3}, [%4];"
                 : "=r"(r0), "=r"(r1), "=r"(r2), "=r"(r3) : "r"(saddr));
}

#define CP_ASYNC16(dst, src) \
    asm volatile("cp.async.cg.shared.global [%0], [%1], 16;" :: "r"(dst), "l"(src))
#define CP_COMMIT() asm volatile("cp.async.commit_group;")
#define CP_WAIT(n)  asm volatile("cp.async.wait_group %0;" :: "n"(n))

// ---------------- threefry2x32 (JAX partitionable, key = (0, 42)) ----------------
__device__ __forceinline__ void threefry2x32_42(unsigned c0, unsigned c1,
                                                unsigned& o0, unsigned& o1)
{
    const unsigned ks0 = 0u;
    const unsigned ks1 = 42u;
    const unsigned ks2 = 0x1BD11BDAu ^ 0u ^ 42u;
    unsigned x0 = c0 + ks0;
    unsigned x1 = c1 + ks1;
#define TF_ROUND(r) { x0 += x1; x1 = (x1 << (r)) | (x1 >> (32 - (r))); x1 ^= x0; }
    TF_ROUND(13) TF_ROUND(15) TF_ROUND(26) TF_ROUND(6)
    x0 += ks1; x1 += ks2 + 1u;
    TF_ROUND(17) TF_ROUND(29) TF_ROUND(16) TF_ROUND(24)
    x0 += ks2; x1 += ks0 + 2u;
    TF_ROUND(13) TF_ROUND(15) TF_ROUND(26) TF_ROUND(6)
    x0 += ks0; x1 += ks1 + 3u;
    TF_ROUND(17) TF_ROUND(29) TF_ROUND(16) TF_ROUND(24)
    x0 += ks1; x1 += ks2 + 4u;
    TF_ROUND(13) TF_ROUND(15) TF_ROUND(26) TF_ROUND(6)
    x0 += ks2; x1 += ks0 + 5u;
#undef TF_ROUND
    o0 = x0; o1 = x1;
}

__device__ __forceinline__ bool keep_bit(unsigned idx)
{
    unsigned a, b;
    threefry2x32_42(0u, idx, a, b);
    return (b >> 31) == 0u;
}

// ============================================================================
// prep: feat->fp16, w1 transpose->fp16, w2 transpose->fp16, zero accumulators
// ============================================================================
#define FEAT_BLOCKS (NROWS * DDIM / (256 * 8))          // 16384
#define W1T_BLOCKS  ((DDIM / 32) * (HDIM / 32))         // 1024
#define W2T_BLOCKS  ((BPADR * HDIM + 255) / 256)        // 192
#define ZERO_BLOCKS ((CDIM * DDIM + 255) / 256)         // 520
#define PREP_BLOCKS (FEAT_BLOCKS + W1T_BLOCKS + W2T_BLOCKS + ZERO_BLOCKS)

__global__ void __launch_bounds__(256) prep_kernel(const float* __restrict__ feat,
                                                   const float* __restrict__ w1,
                                                   const float* __restrict__ w2)
{
    __shared__ float t[32][33];
    const int b = blockIdx.x;
    const int tid = threadIdx.x;

    if (b < FEAT_BLOCKS) {
        size_t i = ((size_t)b * 256 + tid) * 8;
        float4 v0 = *reinterpret_cast<const float4*>(feat + i);
        float4 v1 = *reinterpret_cast<const float4*>(feat + i + 4);
        uint4 o;
        o.x = pack_h2(v0.x, v0.y);
        o.y = pack_h2(v0.z, v0.w);
        o.z = pack_h2(v1.x, v1.y);
        o.w = pack_h2(v1.z, v1.w);
        *reinterpret_cast<uint4*>(&g_feat16[i]) = o;
    } else if (b < FEAT_BLOCKS + W1T_BLOCKS) {
        int q = b - FEAT_BLOCKS;
        int k0 = (q & 63) * 32, n0 = (q >> 6) * 32;
        int x = tid & 31, y = tid >> 5;
#pragma unroll
        for (int i = y; i < 32; i += 8) t[i][x] = w1[(size_t)(k0 + i) * HDIM + n0 + x];
        __syncthreads();
#pragma unroll
        for (int i = y; i < 16; i += 8)
            g_w1Th[(size_t)(n0 + x) * KPAIRS + k0 / 2 + i] = pack_h2(t[2 * i][x], t[2 * i + 1][x]);
    } else if (b < FEAT_BLOCKS + W1T_BLOCKS + W2T_BLOCKS) {
        int i = (b - FEAT_BLOCKS - W1T_BLOCKS) * 256 + tid;
        if (i < BPADR * HDIM) {
            int n = i / HDIM, k = i - n * HDIM;
            g_w2T16[i] = (n < CDIM) ? __float2half_rn(w2[k * CDIM + n]) : __float2half_rn(0.f);
        }
    } else {
        int i = (b - FEAT_BLOCKS - W1T_BLOCKS - W2T_BLOCKS) * 256 + tid;
        if (i < CDIM * DDIM) g_csum[i] = 0.f;
        if (i < CDIM) { g_sump[i] = 0.f; g_cnt[i] = 0; g_fill[i] = 0; }
        if (i == 0) { g_ent = 0.f; g_ce = 0.f; }
    }
}

// ============================================================================
// GEMM1 (fp16, 2-stage cp.async + ldmatrix): g_h16 = dropout(relu(feat@w1+b1))
// CTA 128x128, BK=64, 256 threads, 8 warps of 32x64.
// ============================================================================
#define G1_SMEM (2 * 32768)

__global__ void __launch_bounds__(256) gemm1_fp16(const float* __restrict__ bias)
{
    extern __shared__ __align__(1024) char dsm[];
    __shared__ float sb[128];

    const unsigned sbase = smem_u32(dsm);
    const int tid  = threadIdx.x;
    const int lane = tid & 31;
    const int w    = tid >> 5;
    const int g    = lane >> 2;
    const int t    = lane & 3;
    const int wm   = w & 3;             // 4 row groups of 32
    const int wn   = w >> 2;            // 2 col groups of 64
    const int brow = blockIdx.y * 128;
    const int bcol = blockIdx.x * 128;

    if (tid < 128) sb[tid] = bias[bcol + tid];

    const int NT = DDIM / 64;           // 32
    const int cr = tid >> 3;
    const int cc = tid & 7;

    auto issue_copy = [&](int kt) {
        const unsigned aoff = (kt & 1) * 32768u;
        const unsigned boff = aoff + 16384u;
        const __half* Ag = &g_feat16[(size_t)brow * DDIM + kt * 64];
        const unsigned* Bg = &g_w1Th[(size_t)bcol * KPAIRS + kt * 32];
#pragma unroll
        for (int i = 0; i < 4; i++) {
            int r = cr + 32 * i;
            unsigned dsw = (unsigned)((cc ^ (r & 7)) << 4);
            CP_ASYNC16(sbase + aoff + r * 128 + dsw, Ag + (size_t)r * DDIM + cc * 8);
            CP_ASYNC16(sbase + boff + r * 128 + dsw, Bg + (size_t)r * KPAIRS + cc * 4);
        }
        CP_COMMIT();
    };

    float acc[2][8][4];
#pragma unroll
    for (int i = 0; i < 2; i++)
#pragma unroll
        for (int j = 0; j < 8; j++)
#pragma unroll
            for (int c = 0; c < 4; c++) acc[i][j][c] = 0.f;

    issue_copy(0);

    for (int kt = 0; kt < NT; kt++) {
        if (kt + 1 < NT) { issue_copy(kt + 1); CP_WAIT(1); }
        else             { CP_WAIT(0); }
        __syncthreads();

        const unsigned aoff = (kt & 1) * 32768u;
        const unsigned boff = aoff + 16384u;

        const int arl = (lane & 15);
        const int ach = (lane >> 4);

#pragma unroll
        for (int ks = 0; ks < 4; ks++) {
            unsigned b0[8], b1[8];
#pragma unroll
            for (int gr = 0; gr < 2; gr++) {
                int bn = wn * 64 + gr * 32 + lane;
                unsigned bline = sbase + boff + bn * 128;
                int c0 = (2 * ks) ^ (bn & 7);
                int c1 = (2 * ks + 1) ^ (bn & 7);
                ldsm_x4(b0[gr*4+0], b0[gr*4+1], b0[gr*4+2], b0[gr*4+3], bline + (c0 << 4));
                ldsm_x4(b1[gr*4+0], b1[gr*4+1], b1[gr*4+2], b1[gr*4+3], bline + (c1 << 4));
            }
#pragma unroll
            for (int mt = 0; mt < 2; mt++) {
                int row = wm * 32 + mt * 16 + arl;
                int ch  = (2 * ks + ach) ^ (row & 7);
                unsigned a0, a1, a2, a3;
                ldsm_x4(a0, a1, a2, a3, sbase + aoff + row * 128 + (ch << 4));
#pragma unroll
                for (int nt = 0; nt < 8; nt++)
                    mma_f16(acc[mt][nt], a0, a1, a2, a3, b0[nt], b1[nt]);
            }
        }
        __syncthreads();
    }

#pragma unroll
    for (int mt = 0; mt < 2; mt++) {
#pragma unroll
        for (int h = 0; h < 2; h++) {
            int row = brow + wm * 32 + mt * 16 + g + 8 * h;
#pragma unroll
            for (int nt = 0; nt < 8; nt++) {
                int colL = wn * 64 + nt * 8 + 2 * t;
                unsigned i0 = (unsigned)(row * HDIM + bcol + colL);
                float v0 = fmaxf(acc[mt][nt][2 * h + 0] + sb[colL], 0.f);
                float v1 = fmaxf(acc[mt][nt][2 * h + 1] + sb[colL + 1], 0.f);
                unsigned o = pack_h2(keep_bit(i0)     ? (v0 + v0) : 0.f,
                                     keep_bit(i0 + 1) ? (v1 + v1) : 0.f);
                *reinterpret_cast<unsigned*>(&g_h16[i0]) = o;
            }
        }
    }
}

// ============================================================================
// Skinny GEMMs: 64 rows x 80 cols per block, 128 threads (4 warps x 16 rows).
// Stage: A 8KB | B 12KB ; stride 20480; 2 stages = 40960 B.
// ============================================================================
#define SK_STAGE 20480
#define SK_SMEM  (2 * SK_STAGE)

// ---- logits: A = g_h16, B = g_w2T16; fused stats/argmax/counts ----
__global__ void __launch_bounds__(128) logits_f16(const float* __restrict__ b2)
{
    extern __shared__ __align__(1024) char dsm[];
    const unsigned sbase = smem_u32(dsm);
    const int tid  = threadIdx.x;
    const int lane = tid & 31;
    const int w    = tid >> 5;          // 0..3
    const int g    = lane >> 2;
    const int t    = lane & 3;
    const int row0 = blockIdx.x * 64;
    const int cr   = tid >> 3;          // 0..15
    const int cc   = tid & 7;

    auto issue_copy = [&](int kt) {
        const unsigned aoff = (kt & 1) * (unsigned)SK_STAGE;
        const unsigned boff = aoff + 8192u;
        const __half* Ag = &g_h16[(size_t)row0 * HDIM + kt * 64];
        const __half* Bg = &g_w2T16[kt * 64];
#pragma unroll
        for (int i = 0; i < 4; i++) {
            int r = cr + 16 * i;
            unsigned dsw = (unsigned)((cc ^ (r & 7)) << 4);
            CP_ASYNC16(sbase + aoff + r * 128 + dsw, Ag + (size_t)r * HDIM + cc * 8);
        }
#pragma unroll
        for (int i = 0; i < 6; i++) {
            int q = tid + 128 * i;
            int r = q >> 3, c = q & 7;
            unsigned dsw = (unsigned)((c ^ (r & 7)) << 4);
            CP_ASYNC16(sbase + boff + r * 128 + dsw, Bg + (size_t)r * HDIM + c * 8);
        }
        CP_COMMIT();
    };

    float acc[10][4];
#pragma unroll
    for (int n = 0; n < 10; n++)
#pragma unroll
        for (int c = 0; c < 4; c++) acc[n][c] = 0.f;

    issue_copy(0);
    const int NT = HDIM / 64;   // 8
    for (int kt = 0; kt < NT; kt++) {
        if (kt + 1 < NT) { issue_copy(kt + 1); CP_WAIT(1); }
        else             { CP_WAIT(0); }
        __syncthreads();

        const unsigned aoff = (kt & 1) * (unsigned)SK_STAGE;
        const unsigned boff = aoff + 8192u;
        const int arl = lane & 15;
        const int ach = lane >> 4;

#pragma unroll
        for (int ks = 0; ks < 4; ks++) {
            unsigned b0[12], b1[12];
#pragma unroll
            for (int gr = 0; gr < 3; gr++) {
                int bn = gr * 32 + lane;
                unsigned bline = sbase + boff + bn * 128;
                int c0 = (2 * ks) ^ (bn & 7);
                int c1 = (2 * ks + 1) ^ (bn & 7);
                ldsm_x4(b0[gr*4+0], b0[gr*4+1], b0[gr*4+2], b0[gr*4+3], bline + (c0 << 4));
                ldsm_x4(b1[gr*4+0], b1[gr*4+1], b1[gr*4+2], b1[gr*4+3], bline + (c1 << 4));
            }
            int row = w * 16 + arl;
            int ch  = (2 * ks + ach) ^ (row & 7);
            unsigned a0, a1, a2, a3;
            ldsm_x4(a0, a1, a2, a3, sbase + aoff + row * 128 + (ch << 4));
#pragma unroll
            for (int nt = 0; nt < 10; nt++)
                mma_f16(acc[nt], a0, a1, a2, a3, b0[nt], b1[nt]);
        }
        __syncthreads();
    }

    float su[10][2];
#pragma unroll
    for (int n = 0; n < 10; n++) { su[n][0] = 0.f; su[n][1] = 0.f; }
    float entL = 0.f;

#pragma unroll
    for (int half = 0; half < 2; half++) {
        int row = row0 + w * 16 + g + 8 * half;
        int ci  = 2 * half;

        float v[10][2];
        float m = -1e30f;
#pragma unroll
        for (int nt = 0; nt < 10; nt++)
#pragma unroll
            for (int j = 0; j < 2; j++) {
                int col = nt * 8 + 2 * t + j;
                v[nt][j] = (col < CDIM) ? acc[nt][ci + j] + b2[col] : -1e30f;
                m = fmaxf(m, v[nt][j]);
            }
        m = fmaxf(m, __shfl_xor_sync(0xffffffffu, m, 1));
        m = fmaxf(m, __shfl_xor_sync(0xffffffffu, m, 2));

        float s = 0.f;
#pragma unroll
        for (int nt = 0; nt < 10; nt++)
#pragma unroll
            for (int j = 0; j < 2; j++) {
                int col = nt * 8 + 2 * t + j;
                if (col < CDIM) s += expf(v[nt][j] - m);
            }
        s += __shfl_xor_sync(0xffffffffu, s, 1);
        s += __shfl_xor_sync(0xffffffffu, s, 2);
        float lse = m + logf(s);

        float bv = -1e30f; int bi = CDIM;
#pragma unroll
        for (int nt = 0; nt < 10; nt++)
#pragma unroll
            for (int j = 0; j < 2; j++) {
                int col = nt * 8 + 2 * t + j;
                if (col < CDIM) {
                    float p = expf(v[nt][j] - lse);
                    entL += p * logf(p + 1e-6f);
                    su[nt][j] += p;
                    g_logits[row * CDIM + col] = v[nt][j];
                    if (v[nt][j] > bv || (v[nt][j] == bv && col < bi)) { bv = v[nt][j]; bi = col; }
                }
            }
#pragma unroll
        for (int o = 1; o <= 2; o <<= 1) {
            float ov = __shfl_xor_sync(0xffffffffu, bv, o);
            int   oi = __shfl_xor_sync(0xffffffffu, bi, o);
            if (ov > bv || (ov == bv && oi < bi)) { bv = ov; bi = oi; }
        }
        if (t == 0) {
            g_lse[row]  = lse;
            g_pred[row] = bi;
            atomicAdd(&g_cnt[bi], 1);
        }
    }

#pragma unroll
    for (int o = 16; o > 0; o >>= 1) entL += __shfl_xor_sync(0xffffffffu, entL, o);
    if (lane == 0) atomicAdd(&g_ent, entL);

#pragma unroll
    for (int o = 4; o <= 16; o <<= 1)
#pragma unroll
        for (int nt = 0; nt < 10; nt++)
#pragma unroll
            for (int j = 0; j < 2; j++)
                su[nt][j] += __shfl_xor_sync(0xffffffffu, su[nt][j], o);
    if (g == 0) {
#pragma unroll
        for (int nt = 0; nt < 10; nt++)
#pragma unroll
            for (int j = 0; j < 2; j++) {
                int col = nt * 8 + 2 * t + j;
                if (col < CDIM) atomicAdd(&g_sump[col], su[nt][j]);
            }
    }
}

// ---- scatter: block-aggregated counting sort -> g_perm = (class<<20)|row ----
__global__ void __launch_bounds__(256) scatter_kernel()
{
    __shared__ int sstart[CDIM];
    __shared__ int hist[CDIM];
    __shared__ int basec[CDIM];
    const int tid = threadIdx.x;
    if (tid < CDIM) hist[tid] = 0;
    if (tid == 0) {
        int acc = 0;
        for (int c = 0; c < CDIM; c++) { sstart[c] = acc; acc += g_cnt[c]; }
    }
    __syncthreads();

    int i = blockIdx.x * 256 + tid;
    int c = g_pred[i];
    int loc = atomicAdd(&hist[c], 1);
    __syncthreads();
    if (tid < CDIM && hist[tid] > 0)
        basec[tid] = atomicAdd(&g_fill[tid], hist[tid]);
    __syncthreads();
    g_perm[sstart[c] + basec[c] + loc] = (c << 20) | i;
}

// ---- segsum over fixed 256-row chunks of sorted order ----
#define SEG_CHUNK 256
__global__ void __launch_bounds__(128) segsum_sorted()
{
    __shared__ int spk[SEG_CHUNK];

    const int t    = threadIdx.x;
    const int col2 = blockIdx.x * 128 + t;          // half2 column
    const int r0   = blockIdx.y * SEG_CHUNK;

    for (int i = t; i < SEG_CHUNK; i += 128)
        spk[i] = g_perm[r0 + i];
    __syncthreads();

    const unsigned* f2 = reinterpret_cast<const unsigned*>(g_feat16);
    float rx = 0.f, ry = 0.f;
    int cur = spk[0] >> 20;

    unsigned buf[8];
#pragma unroll
    for (int j = 0; j < 8; j++)
        buf[j] = f2[(size_t)(spk[j] & 0xFFFFF) * (DDIM / 2) + col2];

    for (int base = 0; base < SEG_CHUNK; base += 8) {
        unsigned nbuf[8];
        if (base + 8 < SEG_CHUNK) {
#pragma unroll
            for (int j = 0; j < 8; j++)
                nbuf[j] = f2[(size_t)(spk[base + 8 + j] & 0xFFFFF) * (DDIM / 2) + col2];
        }
#pragma unroll
        for (int j = 0; j < 8; j++) {
            int c = spk[base + j] >> 20;
            if (c != cur) {
                atomicAdd(&g_csum[cur * DDIM + 2 * col2],     rx);
                atomicAdd(&g_csum[cur * DDIM + 2 * col2 + 1], ry);
                rx = 0.f; ry = 0.f; cur = c;
            }
            float2 v = __half22float2(*reinterpret_cast<__half2*>(&buf[j]));
            rx += v.x; ry += v.y;
        }
#pragma unroll
        for (int j = 0; j < 8; j++) buf[j] = nbuf[j];
    }
    atomicAdd(&g_csum[cur * DDIM + 2 * col2],     rx);
    atomicAdd(&g_csum[cur * DDIM + 2 * col2 + 1], ry);
}

// ---- finalize centroids (normalized), K-major fp16; grid = 96 ----
__global__ void __launch_bounds__(256) centroid_f16()
{
    __shared__ float red[256];
    const int c = blockIdx.x;
    const int t = threadIdx.x;
    if (c >= CDIM) {
        for (int d = t; d < DDIM; d += 256) g_cent16[(size_t)c * DDIM + d] = __float2half_rn(0.f);
        return;
    }
    const int cnt = g_cnt[c];
    const float denom = fmaxf((float)cnt, 1.f);

    float ssq = 0.f;
    for (int d = t; d < DDIM; d += 256) {
        float mv = g_csum[c * DDIM + d] / denom;
        ssq += mv * mv;
    }
    red[t] = ssq;
    __syncthreads();
    for (int o = 128; o > 0; o >>= 1) { if (t < o) red[t] += red[t + o]; __syncthreads(); }
    float nrm   = sqrtf(red[0]);
    float scale = (cnt > 0) ? 1.f / (denom * fmaxf(nrm, 1e-12f)) : 0.f;

    for (int d = t; d < DDIM; d += 256)
        g_cent16[(size_t)c * DDIM + d] = __float2half_rn(g_csum[c * DDIM + d] * scale);
}

// ---- sim: A = g_feat16, B = g_cent16; fused argmax + CE ----
__global__ void __launch_bounds__(128) sim_f16()
{
    extern __shared__ __align__(1024) char dsm[];
    const unsigned sbase = smem_u32(dsm);
    const int tid  = threadIdx.x;
    const int lane = tid & 31;
    const int w    = tid >> 5;
    const int t    = lane & 3;
    const int row0 = blockIdx.x * 64;
    const int cr   = tid >> 3;
    const int cc   = tid & 7;

    auto issue_copy = [&](int kt) {
        const unsigned aoff = (kt & 1) * (unsigned)SK_STAGE;
        const unsigned boff = aoff + 8192u;
        const __half* Ag = &g_feat16[(size_t)row0 * DDIM + kt * 64];
        const __half* Bg = &g_cent16[kt * 64];
#pragma unroll
        for (int i = 0; i < 4; i++) {
            int r = cr + 16 * i;
            unsigned dsw = (unsigned)((cc ^ (r & 7)) << 4);
            CP_ASYNC16(sbase + aoff + r * 128 + dsw, Ag + (size_t)r * DDIM + cc * 8);
        }
#pragma unroll
        for (int i = 0; i < 6; i++) {
            int q = tid + 128 * i;
            int r = q >> 3, c = q & 7;
            unsigned dsw = (unsigned)((c ^ (r & 7)) << 4);
            CP_ASYNC16(sbase + boff + r * 128 + dsw, Bg + (size_t)r * DDIM + c * 8);
        }
        CP_COMMIT();
    };

    float acc[10][4];
#pragma unroll
    for (int n = 0; n < 10; n++)
#pragma unroll
        for (int c = 0; c < 4; c++) acc[n][c] = 0.f;

    issue_copy(0);
    const int NT = DDIM / 64;   // 32
    for (int kt = 0; kt < NT; kt++) {
        if (kt + 1 < NT) { issue_copy(kt + 1); CP_WAIT(1); }
        else             { CP_WAIT(0); }
        __syncthreads();

        const unsigned aoff = (kt & 1) * (unsigned)SK_STAGE;
        const unsigned boff = aoff + 8192u;
        const int arl = lane & 15;
        const int ach = lane >> 4;

#pragma unroll
        for (int ks = 0; ks < 4; ks++) {
            unsigned b0[12], b1[12];
#pragma unroll
            for (int gr = 0; gr < 3; gr++) {
                int bn = gr * 32 + lane;
                unsigned bline = sbase + boff + bn * 128;
                int c0 = (2 * ks) ^ (bn & 7);
                int c1 = (2 * ks + 1) ^ (bn & 7);
                ldsm_x4(b0[gr*4+0], b0[gr*4+1], b0[gr*4+2], b0[gr*4+3], bline + (c0 << 4));
                ldsm_x4(b1[gr*4+0], b1[gr*4+1], b1[gr*4+2], b1[gr*4+3], bline + (c1 << 4));
            }
            int row = w * 16 + arl;
            int ch  = (2 * ks + ach) ^ (row & 7);
            unsigned a0, a1, a2, a3;
            ldsm_x4(a0, a1, a2, a3, sbase + aoff + row * 128 + (ch << 4));
#pragma unroll
            for (int nt = 0; nt < 10; nt++)
                mma_f16(acc[nt], a0, a1, a2, a3, b0[nt], b1[nt]);
        }
        __syncthreads();
    }

    const int g = lane >> 2;
    float ceL = 0.f;
#pragma unroll
    for (int half = 0; half < 2; half++) {
        int row = row0 + w * 16 + g + 8 * half;
        int ci  = 2 * half;

        float bv = -1e30f; int bi = CDIM;
#pragma unroll
        for (int nt = 0; nt < 10; nt++)
#pragma unroll
            for (int j = 0; j < 2; j++) {
                int col = nt * 8 + 2 * t + j;
                if (col < CDIM) {
                    float vv = acc[nt][ci + j];
                    if (vv > bv || (vv == bv && col < bi)) { bv = vv; bi = col; }
                }
            }
#pragma unroll
        for (int o = 1; o <= 2; o <<= 1) {
            float ov = __shfl_xor_sync(0xffffffffu, bv, o);
            int   oi = __shfl_xor_sync(0xffffffffu, bi, o);
            if (ov > bv || (ov == bv && oi < bi)) { bv = ov; bi = oi; }
        }
        if (t == 0)
            ceL += g_lse[row] - g_logits[row * CDIM + bi];
    }
#pragma unroll
    for (int o = 16; o > 0; o >>= 1) ceL += __shfl_xor_sync(0xffffffffu, ceL, o);
    if (lane == 0) atomicAdd(&g_ce, ceL);
}

// ---------------- final scalar ----------------
__global__ void finalize_kernel(float* __restrict__ out)
{
    __shared__ float red[128];
    int t = threadIdx.x;
    float v = 0.f;
    if (t < CDIM) {
        float mp = g_sump[t] * (1.f / NROWS);
        v = mp * logf(mp + 1e-6f);
    }
    red[t] = v;
    __syncthreads();
    for (int o = 64; o > 0; o >>= 1) { if (t < o) red[t] += red[t + o]; __syncthreads(); }
    if (t == 0) {
        float entropy = -g_ent * (1.f / NROWS);
        float ce      =  g_ce  * (1.f / NROWS);
        out[0] = entropy + red[0] + 0.3f * ce;
    }
}

// ---------------- launch ----------------
extern "C" void kernel_launch(void* const* d_in, const int* in_sizes, int n_in,
                              void* d_out, int out_size)
{
    const float* feat = (const float*)d_in[0];
    const float* w1   = (const float*)d_in[1];
    const float* b1   = (const float*)d_in[2];
    const float* w2   = (const float*)d_in[3];
    const float* b2   = (const float*)d_in[4];
    float* out = (float*)d_out;

    cudaFuncSetAttribute(gemm1_fp16, cudaFuncAttributeMaxDynamicSharedMemorySize, G1_SMEM);
    cudaFuncSetAttribute(logits_f16, cudaFuncAttributeMaxDynamicSharedMemorySize, SK_SMEM);
    cudaFuncSetAttribute(sim_f16,    cudaFuncAttributeMaxDynamicSharedMemorySize, SK_SMEM);

    prep_kernel<<<PREP_BLOCKS, 256>>>(feat, w1, w2);
    gemm1_fp16<<<dim3(HDIM / 128, NROWS / 128), 256, G1_SMEM>>>(b1);
    logits_f16<<<NROWS / 64, 128, SK_SMEM>>>(b2);
    scatter_kernel<<<NROWS / 256, 256>>>();
    segsum_sorted<<<dim3(DDIM / 256, NROWS / SEG_CHUNK), 128>>>();
    centroid_f16<<<BPADR, 256>>>();
    sim_f16<<<NROWS / 64, 128, SK_SMEM>>>();
    finalize_kernel<<<1, 128>>>(out);
}